// round 1
// baseline (speedup 1.0000x reference)
#include <cuda_runtime.h>
#include <math.h>

#define TOKENS 2048
#define HID    1024
#define NEXP   64
#define INTER  512
#define TOPK   8
#define NGRP   8
#define TOPKG  4

// ---------------- scratch (static device globals; no allocation) ------------
__device__ float g_scores[TOKENS * NEXP];
__device__ int   g_cnt[NEXP];
__device__ int   g_tok[NEXP * TOKENS];
__device__ float g_wt[NEXP * TOKENS];
__device__ float g_h[(size_t)NEXP * TOKENS * INTER];   // per-expert gathered SwiGLU output

__global__ void zero_cnt_kernel() {
    if (threadIdx.x < NEXP) g_cnt[threadIdx.x] = 0;
}

// ---------------- router: scores = sigmoid(x @ gate_w^T) --------------------
// BM=128 tokens, N=64 experts, BK=16. 128 threads, 8x8 micro-tile.
__global__ __launch_bounds__(128) void router_kernel(const float* __restrict__ x,
                                                     const float* __restrict__ gw) {
    __shared__ float Xs[16][132];
    __shared__ float Gs[16][68];
    const int m0  = blockIdx.x * 128;
    const int tid = threadIdx.x;
    const int ty  = tid >> 3;   // 0..15 (8 rows each)
    const int tx  = tid & 7;    // 0..7  (8 cols each)

    float acc[8][8];
#pragma unroll
    for (int i = 0; i < 8; i++)
#pragma unroll
        for (int j = 0; j < 8; j++) acc[i][j] = 0.f;

    const float* xrow = x + (size_t)(m0 + tid) * HID;
    const float* grow = gw + (size_t)tid * HID;

    for (int k0 = 0; k0 < HID; k0 += 16) {
#pragma unroll
        for (int i = 0; i < 4; i++) {
            float4 v = *(const float4*)(xrow + k0 + i * 4);
            Xs[i * 4 + 0][tid] = v.x; Xs[i * 4 + 1][tid] = v.y;
            Xs[i * 4 + 2][tid] = v.z; Xs[i * 4 + 3][tid] = v.w;
        }
        if (tid < 64) {
#pragma unroll
            for (int i = 0; i < 4; i++) {
                float4 v = *(const float4*)(grow + k0 + i * 4);
                Gs[i * 4 + 0][tid] = v.x; Gs[i * 4 + 1][tid] = v.y;
                Gs[i * 4 + 2][tid] = v.z; Gs[i * 4 + 3][tid] = v.w;
            }
        }
        __syncthreads();
#pragma unroll
        for (int k = 0; k < 16; k++) {
            float a[8], b[8];
            *(float4*)(a)     = *(const float4*)&Xs[k][ty * 8];
            *(float4*)(a + 4) = *(const float4*)&Xs[k][ty * 8 + 4];
            *(float4*)(b)     = *(const float4*)&Gs[k][tx * 8];
            *(float4*)(b + 4) = *(const float4*)&Gs[k][tx * 8 + 4];
#pragma unroll
            for (int i = 0; i < 8; i++)
#pragma unroll
                for (int j = 0; j < 8; j++) acc[i][j] += a[i] * b[j];
        }
        __syncthreads();
    }

#pragma unroll
    for (int i = 0; i < 8; i++) {
        int t = m0 + ty * 8 + i;
#pragma unroll
        for (int j = 0; j < 8; j++) {
            g_scores[(size_t)t * NEXP + tx * 8 + j] = 1.f / (1.f + expf(-acc[i][j]));
        }
    }
}

// ---------------- grouped top-k routing (exact, matches jax.lax.top_k) ------
__global__ void topk_kernel(const float* __restrict__ bias) {
    int t = blockIdx.x * blockDim.x + threadIdx.x;
    if (t >= TOKENS) return;

    float sraw[NEXP], sb[NEXP];
    const float* sc = g_scores + (size_t)t * NEXP;
#pragma unroll
    for (int e = 0; e < NEXP; e++) { sraw[e] = sc[e]; sb[e] = sraw[e] + bias[e]; }

    // group score = sum of top-2 (selection scores)
    float gs[NGRP];
#pragma unroll
    for (int g = 0; g < NGRP; g++) {
        float m1 = -1e30f, m2 = -1e30f;
#pragma unroll
        for (int j = 0; j < NEXP / NGRP; j++) {
            float v = sb[g * (NEXP / NGRP) + j];
            if (v > m1) { m2 = m1; m1 = v; } else if (v > m2) { m2 = v; }
        }
        gs[g] = m1 + m2;
    }

    // top-4 groups (strict > keeps lowest index on ties, same as jax)
    unsigned gsel = 0;
    for (int it = 0; it < TOPKG; it++) {
        int best = -1; float bv = -1e30f;
#pragma unroll
        for (int g = 0; g < NGRP; g++)
            if (!((gsel >> g) & 1u) && gs[g] > bv) { bv = gs[g]; best = g; }
        gsel |= 1u << best;
    }

    // top-8 experts within selected groups
    unsigned long long esel = 0ull;
    int   ids[TOPK];
    float w[TOPK];
    float wsum = 0.f;
    for (int it = 0; it < TOPK; it++) {
        int best = -1; float bv = -1e30f;
#pragma unroll
        for (int e = 0; e < NEXP; e++) {
            if (((gsel >> (e >> 3)) & 1u) && !((esel >> e) & 1ull)) {
                float v = sb[e];
                if (v > bv) { bv = v; best = e; }
            }
        }
        esel |= 1ull << best;
        ids[it] = best;
        w[it]   = sraw[best];        // weights use raw sigmoid scores (no bias)
        wsum   += sraw[best];
    }
    float inv = 1.f / wsum;

    for (int it = 0; it < TOPK; it++) {
        int e   = ids[it];
        int pos = atomicAdd(&g_cnt[e], 1);
        g_tok[e * TOKENS + pos] = t;
        g_wt[e * TOKENS + pos]  = w[it] * inv;
    }
}

// ---------------- expert GEMM1: h = silu(x@Wg^T) * (x@Wu^T) ------------------
// grid (8 n-tiles of 64 inter dims, 32 m-tiles of 64 tokens, 64 experts)
__global__ __launch_bounds__(128) void w13_kernel(const float* __restrict__ x,
                                                  const float* __restrict__ w13) {
    const int e   = blockIdx.z;
    const int cnt = g_cnt[e];
    const int m0  = blockIdx.y * 64;
    if (m0 >= cnt) return;
    const int n0  = blockIdx.x * 64;

    __shared__ float Xs[16][68];
    __shared__ float Ws[16][132];
    __shared__ int   stok[64];

    const int tid = threadIdx.x;
    if (tid < 64) {
        int m = m0 + tid;
        stok[tid] = (m < cnt) ? g_tok[e * TOKENS + m] : -1;
    }
    __syncthreads();

    const int ty = tid >> 4;   // 0..7  rows (8 each)
    const int tx = tid & 15;   // 0..15 cols (4 g-cols + 4 u-cols each)

    float acc[8][8];
#pragma unroll
    for (int i = 0; i < 8; i++)
#pragma unroll
        for (int j = 0; j < 8; j++) acc[i][j] = 0.f;

    const float* wbase = w13 + (size_t)e * (2 * INTER) * HID;
    const int lr = tid >> 1;          // 0..63
    const int lp = (tid & 1) * 8;     // 0 or 8
    const int tokr = stok[lr];
    const float* xrow = (tokr >= 0) ? (x + (size_t)tokr * HID) : x;
    const int wr  = tid;              // 0..127
    const int row = (wr < 64) ? (n0 + wr) : (INTER + n0 + (wr - 64));
    const float* wrow = wbase + (size_t)row * HID;

    for (int k0 = 0; k0 < HID; k0 += 16) {
        float4 a0, a1;
        if (tokr >= 0) {
            a0 = *(const float4*)(xrow + k0 + lp);
            a1 = *(const float4*)(xrow + k0 + lp + 4);
        } else {
            a0 = make_float4(0.f, 0.f, 0.f, 0.f); a1 = a0;
        }
        Xs[lp + 0][lr] = a0.x; Xs[lp + 1][lr] = a0.y; Xs[lp + 2][lr] = a0.z; Xs[lp + 3][lr] = a0.w;
        Xs[lp + 4][lr] = a1.x; Xs[lp + 5][lr] = a1.y; Xs[lp + 6][lr] = a1.z; Xs[lp + 7][lr] = a1.w;
#pragma unroll
        for (int i = 0; i < 4; i++) {
            float4 v = *(const float4*)(wrow + k0 + i * 4);
            Ws[i * 4 + 0][wr] = v.x; Ws[i * 4 + 1][wr] = v.y;
            Ws[i * 4 + 2][wr] = v.z; Ws[i * 4 + 3][wr] = v.w;
        }
        __syncthreads();
#pragma unroll
        for (int k = 0; k < 16; k++) {
            float a[8], b[8];
            *(float4*)(a)     = *(const float4*)&Xs[k][ty * 8];
            *(float4*)(a + 4) = *(const float4*)&Xs[k][ty * 8 + 4];
            *(float4*)(b)     = *(const float4*)&Ws[k][tx * 4];          // gate cols
            *(float4*)(b + 4) = *(const float4*)&Ws[k][64 + tx * 4];     // up cols
#pragma unroll
            for (int i = 0; i < 8; i++)
#pragma unroll
                for (int j = 0; j < 8; j++) acc[i][j] += a[i] * b[j];
        }
        __syncthreads();
    }

#pragma unroll
    for (int i = 0; i < 8; i++) {
        int m = m0 + ty * 8 + i;
        if (m >= cnt) continue;
        size_t hbase = ((size_t)e * TOKENS + m) * INTER + n0 + tx * 4;
#pragma unroll
        for (int j = 0; j < 4; j++) {
            float gg = acc[i][j];
            float uu = acc[i][4 + j];
            g_h[hbase + j] = gg / (1.f + expf(-gg)) * uu;   // silu(g)*u
        }
    }
}

// ---------------- expert GEMM2: y += wt * (h @ W2^T) -------------------------
// grid (8 n-tiles of 128 out dims, 32 m-tiles of 64 tokens, 64 experts)
__global__ __launch_bounds__(128) void w2_kernel(const float* __restrict__ w2,
                                                 float* __restrict__ y) {
    const int e   = blockIdx.z;
    const int cnt = g_cnt[e];
    const int m0  = blockIdx.y * 64;
    if (m0 >= cnt) return;
    const int n0  = blockIdx.x * 128;

    __shared__ float Hs[16][68];
    __shared__ float Ws[16][132];
    __shared__ int   stok[64];
    __shared__ float swt[64];

    const int tid = threadIdx.x;
    if (tid < 64) {
        int m = m0 + tid;
        bool v = m < cnt;
        stok[tid] = v ? g_tok[e * TOKENS + m] : -1;
        swt[tid]  = v ? g_wt[e * TOKENS + m] : 0.f;
    }
    __syncthreads();

    const int ty = tid >> 4;   // 0..7
    const int tx = tid & 15;   // 0..15 (8 cols each -> 128)

    float acc[8][8];
#pragma unroll
    for (int i = 0; i < 8; i++)
#pragma unroll
        for (int j = 0; j < 8; j++) acc[i][j] = 0.f;

    const float* wbase = w2 + (size_t)e * HID * INTER;
    const int lr = tid >> 1;
    const int lp = (tid & 1) * 8;
    const bool hvalid = (m0 + lr) < cnt;
    const float* hrow = g_h + ((size_t)e * TOKENS + (m0 + lr)) * INTER;
    const float* wrow = wbase + (size_t)(n0 + tid) * INTER;

    for (int k0 = 0; k0 < INTER; k0 += 16) {
        float4 a0, a1;
        if (hvalid) {
            a0 = *(const float4*)(hrow + k0 + lp);
            a1 = *(const float4*)(hrow + k0 + lp + 4);
        } else {
            a0 = make_float4(0.f, 0.f, 0.f, 0.f); a1 = a0;
        }
        Hs[lp + 0][lr] = a0.x; Hs[lp + 1][lr] = a0.y; Hs[lp + 2][lr] = a0.z; Hs[lp + 3][lr] = a0.w;
        Hs[lp + 4][lr] = a1.x; Hs[lp + 5][lr] = a1.y; Hs[lp + 6][lr] = a1.z; Hs[lp + 7][lr] = a1.w;
#pragma unroll
        for (int i = 0; i < 4; i++) {
            float4 v = *(const float4*)(wrow + k0 + i * 4);
            Ws[i * 4 + 0][tid] = v.x; Ws[i * 4 + 1][tid] = v.y;
            Ws[i * 4 + 2][tid] = v.z; Ws[i * 4 + 3][tid] = v.w;
        }
        __syncthreads();
#pragma unroll
        for (int k = 0; k < 16; k++) {
            float a[8], b[8];
            *(float4*)(a)     = *(const float4*)&Hs[k][ty * 8];
            *(float4*)(a + 4) = *(const float4*)&Hs[k][ty * 8 + 4];
            *(float4*)(b)     = *(const float4*)&Ws[k][tx * 8];
            *(float4*)(b + 4) = *(const float4*)&Ws[k][tx * 8 + 4];
#pragma unroll
            for (int i = 0; i < 8; i++)
#pragma unroll
                for (int j = 0; j < 8; j++) acc[i][j] += a[i] * b[j];
        }
        __syncthreads();
    }

#pragma unroll
    for (int i = 0; i < 8; i++) {
        int m = m0 + ty * 8 + i;
        if (m >= cnt) continue;
        int   tok = stok[ty * 8 + i];
        float wt  = swt[ty * 8 + i];
        float* yrow = y + (size_t)tok * HID + n0 + tx * 8;
#pragma unroll
        for (int j = 0; j < 8; j++) atomicAdd(&yrow[j], wt * acc[i][j]);
    }
}

// ---------------- launch ----------------------------------------------------
extern "C" void kernel_launch(void* const* d_in, const int* in_sizes, int n_in,
                              void* d_out, int out_size) {
    const float* x    = (const float*)d_in[0];   // [2048,1024]
    const float* gw   = (const float*)d_in[1];   // [64,1024]
    const float* bias = (const float*)d_in[2];   // [64]
    const float* w13  = (const float*)d_in[3];   // [64,1024,1024]
    const float* w2   = (const float*)d_in[4];   // [64,1024,512]
    float* y = (float*)d_out;                    // [2048,1024]

    cudaMemsetAsync(y, 0, (size_t)TOKENS * HID * sizeof(float), 0);
    zero_cnt_kernel<<<1, 64>>>();
    router_kernel<<<TOKENS / 128, 128>>>(x, gw);
    topk_kernel<<<TOKENS / 256, 256>>>(bias);
    w13_kernel<<<dim3(INTER / 64, TOKENS / 64, NEXP), 128>>>(x, w13);
    w2_kernel<<<dim3(HID / 128, TOKENS / 64, NEXP), 128>>>(w2, y);
}

// round 2
// speedup vs baseline: 1.3199x; 1.3199x over previous
#include <cuda_runtime.h>
#include <math.h>
#include <stdint.h>

#define TOKENS 2048
#define HID    1024
#define NEXP   64
#define INTER  512
#define TOPK   8
#define NGRP   8
#define TOPKG  4

// ---------------- scratch (static device globals; no allocation) ------------
__device__ float g_scores[TOKENS * NEXP];
__device__ int   g_cnt[NEXP];
__device__ int   g_tok[NEXP * TOKENS];
__device__ float g_wt[NEXP * TOKENS];
__device__ float g_h[(size_t)NEXP * TOKENS * INTER];   // per-expert gathered SwiGLU output

__global__ void zero_cnt_kernel() {
    if (threadIdx.x < NEXP) g_cnt[threadIdx.x] = 0;
}

// ---------------- helpers ----------------------------------------------------
__device__ __forceinline__ uint32_t f2tf32(float f) {
    uint32_t u;
    asm("cvt.rna.tf32.f32 %0, %1;" : "=r"(u) : "f"(f));
    return u;
}

__device__ __forceinline__ void mma_tf32(float c[4], const uint32_t a[4], const uint32_t b[2]) {
    asm volatile(
        "mma.sync.aligned.m16n8k8.row.col.f32.tf32.tf32.f32 "
        "{%0,%1,%2,%3},{%4,%5,%6,%7},{%8,%9},{%0,%1,%2,%3};"
        : "+f"(c[0]), "+f"(c[1]), "+f"(c[2]), "+f"(c[3])
        : "r"(a[0]), "r"(a[1]), "r"(a[2]), "r"(a[3]), "r"(b[0]), "r"(b[1]));
}

__device__ __forceinline__ float silu(float g) {
    return g / (1.f + expf(-g));
}

// ---------------- router: scores = sigmoid(x @ gate_w^T) --------------------
__global__ __launch_bounds__(128) void router_kernel(const float* __restrict__ x,
                                                     const float* __restrict__ gw) {
    __shared__ float Xs[16][132];
    __shared__ float Gs[16][68];
    const int m0  = blockIdx.x * 128;
    const int tid = threadIdx.x;
    const int ty  = tid >> 3;
    const int tx  = tid & 7;

    float acc[8][8];
#pragma unroll
    for (int i = 0; i < 8; i++)
#pragma unroll
        for (int j = 0; j < 8; j++) acc[i][j] = 0.f;

    const float* xrow = x + (size_t)(m0 + tid) * HID;
    const float* grow = gw + (size_t)tid * HID;

    for (int k0 = 0; k0 < HID; k0 += 16) {
#pragma unroll
        for (int i = 0; i < 4; i++) {
            float4 v = *(const float4*)(xrow + k0 + i * 4);
            Xs[i * 4 + 0][tid] = v.x; Xs[i * 4 + 1][tid] = v.y;
            Xs[i * 4 + 2][tid] = v.z; Xs[i * 4 + 3][tid] = v.w;
        }
        if (tid < 64) {
#pragma unroll
            for (int i = 0; i < 4; i++) {
                float4 v = *(const float4*)(grow + k0 + i * 4);
                Gs[i * 4 + 0][tid] = v.x; Gs[i * 4 + 1][tid] = v.y;
                Gs[i * 4 + 2][tid] = v.z; Gs[i * 4 + 3][tid] = v.w;
            }
        }
        __syncthreads();
#pragma unroll
        for (int k = 0; k < 16; k++) {
            float a[8], b[8];
            *(float4*)(a)     = *(const float4*)&Xs[k][ty * 8];
            *(float4*)(a + 4) = *(const float4*)&Xs[k][ty * 8 + 4];
            *(float4*)(b)     = *(const float4*)&Gs[k][tx * 8];
            *(float4*)(b + 4) = *(const float4*)&Gs[k][tx * 8 + 4];
#pragma unroll
            for (int i = 0; i < 8; i++)
#pragma unroll
                for (int j = 0; j < 8; j++) acc[i][j] += a[i] * b[j];
        }
        __syncthreads();
    }

#pragma unroll
    for (int i = 0; i < 8; i++) {
        int t = m0 + ty * 8 + i;
#pragma unroll
        for (int j = 0; j < 8; j++) {
            g_scores[(size_t)t * NEXP + tx * 8 + j] = 1.f / (1.f + expf(-acc[i][j]));
        }
    }
}

// ---------------- grouped top-k routing (exact) ------------------------------
__global__ void topk_kernel(const float* __restrict__ bias) {
    int t = blockIdx.x * blockDim.x + threadIdx.x;
    if (t >= TOKENS) return;

    float sraw[NEXP], sb[NEXP];
    const float* sc = g_scores + (size_t)t * NEXP;
#pragma unroll
    for (int e = 0; e < NEXP; e++) { sraw[e] = sc[e]; sb[e] = sraw[e] + bias[e]; }

    float gs[NGRP];
#pragma unroll
    for (int g = 0; g < NGRP; g++) {
        float m1 = -1e30f, m2 = -1e30f;
#pragma unroll
        for (int j = 0; j < NEXP / NGRP; j++) {
            float v = sb[g * (NEXP / NGRP) + j];
            if (v > m1) { m2 = m1; m1 = v; } else if (v > m2) { m2 = v; }
        }
        gs[g] = m1 + m2;
    }

    unsigned gsel = 0;
    for (int it = 0; it < TOPKG; it++) {
        int best = -1; float bv = -1e30f;
#pragma unroll
        for (int g = 0; g < NGRP; g++)
            if (!((gsel >> g) & 1u) && gs[g] > bv) { bv = gs[g]; best = g; }
        gsel |= 1u << best;
    }

    unsigned long long esel = 0ull;
    int   ids[TOPK];
    float w[TOPK];
    float wsum = 0.f;
    for (int it = 0; it < TOPK; it++) {
        int best = -1; float bv = -1e30f;
#pragma unroll
        for (int e = 0; e < NEXP; e++) {
            if (((gsel >> (e >> 3)) & 1u) && !((esel >> e) & 1ull)) {
                float v = sb[e];
                if (v > bv) { bv = v; best = e; }
            }
        }
        esel |= 1ull << best;
        ids[it] = best;
        w[it]   = sraw[best];
        wsum   += sraw[best];
    }
    float inv = 1.f / wsum;

    for (int it = 0; it < TOPK; it++) {
        int e   = ids[it];
        int pos = atomicAdd(&g_cnt[e], 1);
        g_tok[e * TOKENS + pos] = t;
        g_wt[e * TOKENS + pos]  = w[it] * inv;
    }
}

// ---------------- expert GEMM1 (tf32 mma): h = silu(x@Wg^T)*(x@Wu^T) ---------
// block tile: 64 tokens x (64 gate + 64 up), BK=32, 256 threads, 8 warps (2M x 4N)
#define BK 32
__global__ __launch_bounds__(256) void w13_mma_kernel(const float* __restrict__ x,
                                                      const float* __restrict__ w13) {
    const int e   = blockIdx.z;
    const int cnt = g_cnt[e];
    const int m0  = blockIdx.y * 64;
    if (m0 >= cnt) return;
    const int n0  = blockIdx.x * 64;   // gate col base within INTER

    __shared__ uint32_t Xs[BK][72];    // [k][m], tf32 bits
    __shared__ uint32_t Ws[BK][136];   // [k][c], c: 0-63 gate rows, 64-127 up rows
    __shared__ int      stok[64];

    const int tid  = threadIdx.x;
    const int lane = tid & 31;
    const int wrp  = tid >> 5;
    const int wm   = wrp & 1;          // 0,1 : 32-row half
    const int wn   = wrp >> 1;         // 0..3: 16 gate cols + 16 up cols
    const int t4   = lane & 3;
    const int g8   = lane >> 2;

    if (tid < 64) {
        int m = m0 + tid;
        stok[tid] = (m < cnt) ? g_tok[e * TOKENS + m] : -1;
    }
    __syncthreads();

    // loader roles
    const int lm   = tid & 63;              // Xs row
    const int lk   = (tid >> 6) * 8;        // Xs k offset (0,8,16,24)
    const int tokr = stok[lm];
    const float* xrow = (tokr >= 0) ? (x + (size_t)tokr * HID) : x;

    const int lc   = tid & 127;             // Ws col
    const int lkw  = (tid >> 7) * 16;       // Ws k offset (0,16)
    const int wrow_idx = (lc < 64) ? (n0 + lc) : (INTER + n0 + (lc - 64));
    const float* wrow = w13 + (size_t)e * (2 * INTER) * HID + (size_t)wrow_idx * HID;

    float4 xr0, xr1, wr[4];

    auto load_g = [&](int k0) {
        if (tokr >= 0) {
            xr0 = *(const float4*)(xrow + k0 + lk);
            xr1 = *(const float4*)(xrow + k0 + lk + 4);
        } else {
            xr0 = make_float4(0.f, 0.f, 0.f, 0.f); xr1 = xr0;
        }
#pragma unroll
        for (int j = 0; j < 4; j++)
            wr[j] = *(const float4*)(wrow + k0 + lkw + j * 4);
    };
    auto store_s = [&]() {
        Xs[lk + 0][lm] = f2tf32(xr0.x); Xs[lk + 1][lm] = f2tf32(xr0.y);
        Xs[lk + 2][lm] = f2tf32(xr0.z); Xs[lk + 3][lm] = f2tf32(xr0.w);
        Xs[lk + 4][lm] = f2tf32(xr1.x); Xs[lk + 5][lm] = f2tf32(xr1.y);
        Xs[lk + 6][lm] = f2tf32(xr1.z); Xs[lk + 7][lm] = f2tf32(xr1.w);
#pragma unroll
        for (int j = 0; j < 4; j++) {
            Ws[lkw + j * 4 + 0][lc] = f2tf32(wr[j].x);
            Ws[lkw + j * 4 + 1][lc] = f2tf32(wr[j].y);
            Ws[lkw + j * 4 + 2][lc] = f2tf32(wr[j].z);
            Ws[lkw + j * 4 + 3][lc] = f2tf32(wr[j].w);
        }
    };

    float acc[2][4][4];
#pragma unroll
    for (int i = 0; i < 2; i++)
#pragma unroll
        for (int j = 0; j < 4; j++)
#pragma unroll
            for (int c = 0; c < 4; c++) acc[i][j][c] = 0.f;

    const int NIT = HID / BK;   // 32
    load_g(0);
    store_s();
    __syncthreads();

    for (int it = 0; it < NIT; it++) {
        if (it + 1 < NIT) load_g((it + 1) * BK);

#pragma unroll
        for (int ks = 0; ks < BK / 8; ks++) {
            const int kk = ks * 8;
            uint32_t a[2][4];
#pragma unroll
            for (int mf = 0; mf < 2; mf++) {
                int mrow = wm * 32 + mf * 16 + g8;
                a[mf][0] = Xs[kk + t4][mrow];
                a[mf][1] = Xs[kk + t4][mrow + 8];
                a[mf][2] = Xs[kk + t4 + 4][mrow];
                a[mf][3] = Xs[kk + t4 + 4][mrow + 8];
            }
            uint32_t b[4][2];
#pragma unroll
            for (int nf = 0; nf < 4; nf++) {
                int col = (nf < 2) ? (wn * 16 + nf * 8) : (64 + wn * 16 + (nf - 2) * 8);
                col += g8;
                b[nf][0] = Ws[kk + t4][col];
                b[nf][1] = Ws[kk + t4 + 4][col];
            }
#pragma unroll
            for (int mf = 0; mf < 2; mf++)
#pragma unroll
                for (int nf = 0; nf < 4; nf++) mma_tf32(acc[mf][nf], a[mf], b[nf]);
        }
        __syncthreads();
        if (it + 1 < NIT) { store_s(); __syncthreads(); }
    }

    // epilogue: SwiGLU fuse gate (nf 0,1) with up (nf 2,3)
#pragma unroll
    for (int mf = 0; mf < 2; mf++) {
#pragma unroll
        for (int j = 0; j < 2; j++) {
            int cn = n0 + wn * 16 + j * 8 + 2 * t4;
            int r0 = wm * 32 + mf * 16 + g8;
            int r1 = r0 + 8;
            if (m0 + r0 < cnt) {
                float2 o;
                o.x = silu(acc[mf][j][0]) * acc[mf][j + 2][0];
                o.y = silu(acc[mf][j][1]) * acc[mf][j + 2][1];
                *(float2*)&g_h[((size_t)e * TOKENS + m0 + r0) * INTER + cn] = o;
            }
            if (m0 + r1 < cnt) {
                float2 o;
                o.x = silu(acc[mf][j][2]) * acc[mf][j + 2][2];
                o.y = silu(acc[mf][j][3]) * acc[mf][j + 2][3];
                *(float2*)&g_h[((size_t)e * TOKENS + m0 + r1) * INTER + cn] = o;
            }
        }
    }
}

// ---------------- expert GEMM2 (tf32 mma): y += wt * (h @ W2^T) --------------
// block tile: 64 tokens x 128 hid, BK=32, 256 threads, 8 warps (2M x 4N)
__global__ __launch_bounds__(256) void w2_mma_kernel(const float* __restrict__ w2,
                                                     float* __restrict__ y) {
    const int e   = blockIdx.z;
    const int cnt = g_cnt[e];
    const int m0  = blockIdx.y * 64;
    if (m0 >= cnt) return;
    const int n0  = blockIdx.x * 128;

    __shared__ uint32_t Hs[BK][72];
    __shared__ uint32_t Ws[BK][136];
    __shared__ int      stok[64];
    __shared__ float    swt[64];

    const int tid  = threadIdx.x;
    const int lane = tid & 31;
    const int wrp  = tid >> 5;
    const int wm   = wrp & 1;
    const int wn   = wrp >> 1;         // 0..3 : 32 cols each
    const int t4   = lane & 3;
    const int g8   = lane >> 2;

    if (tid < 64) {
        int m = m0 + tid;
        bool v = m < cnt;
        stok[tid] = v ? g_tok[e * TOKENS + m] : -1;
        swt[tid]  = v ? g_wt[e * TOKENS + m] : 0.f;
    }
    __syncthreads();

    const int lm = tid & 63;
    const int lk = (tid >> 6) * 8;
    const bool hvalid = (m0 + lm) < cnt;
    const float* hrow = g_h + ((size_t)e * TOKENS + m0 + lm) * INTER;

    const int lc  = tid & 127;
    const int lkw = (tid >> 7) * 16;
    const float* wrow = w2 + (size_t)e * HID * INTER + (size_t)(n0 + lc) * INTER;

    float4 hr0, hr1, wr[4];

    auto load_g = [&](int k0) {
        if (hvalid) {
            hr0 = *(const float4*)(hrow + k0 + lk);
            hr1 = *(const float4*)(hrow + k0 + lk + 4);
        } else {
            hr0 = make_float4(0.f, 0.f, 0.f, 0.f); hr1 = hr0;
        }
#pragma unroll
        for (int j = 0; j < 4; j++)
            wr[j] = *(const float4*)(wrow + k0 + lkw + j * 4);
    };
    auto store_s = [&]() {
        Hs[lk + 0][lm] = f2tf32(hr0.x); Hs[lk + 1][lm] = f2tf32(hr0.y);
        Hs[lk + 2][lm] = f2tf32(hr0.z); Hs[lk + 3][lm] = f2tf32(hr0.w);
        Hs[lk + 4][lm] = f2tf32(hr1.x); Hs[lk + 5][lm] = f2tf32(hr1.y);
        Hs[lk + 6][lm] = f2tf32(hr1.z); Hs[lk + 7][lm] = f2tf32(hr1.w);
#pragma unroll
        for (int j = 0; j < 4; j++) {
            Ws[lkw + j * 4 + 0][lc] = f2tf32(wr[j].x);
            Ws[lkw + j * 4 + 1][lc] = f2tf32(wr[j].y);
            Ws[lkw + j * 4 + 2][lc] = f2tf32(wr[j].z);
            Ws[lkw + j * 4 + 3][lc] = f2tf32(wr[j].w);
        }
    };

    float acc[2][4][4];
#pragma unroll
    for (int i = 0; i < 2; i++)
#pragma unroll
        for (int j = 0; j < 4; j++)
#pragma unroll
            for (int c = 0; c < 4; c++) acc[i][j][c] = 0.f;

    const int NIT = INTER / BK;   // 16
    load_g(0);
    store_s();
    __syncthreads();

    for (int it = 0; it < NIT; it++) {
        if (it + 1 < NIT) load_g((it + 1) * BK);

#pragma unroll
        for (int ks = 0; ks < BK / 8; ks++) {
            const int kk = ks * 8;
            uint32_t a[2][4];
#pragma unroll
            for (int mf = 0; mf < 2; mf++) {
                int mrow = wm * 32 + mf * 16 + g8;
                a[mf][0] = Hs[kk + t4][mrow];
                a[mf][1] = Hs[kk + t4][mrow + 8];
                a[mf][2] = Hs[kk + t4 + 4][mrow];
                a[mf][3] = Hs[kk + t4 + 4][mrow + 8];
            }
            uint32_t b[4][2];
#pragma unroll
            for (int nf = 0; nf < 4; nf++) {
                int col = wn * 32 + nf * 8 + g8;
                b[nf][0] = Ws[kk + t4][col];
                b[nf][1] = Ws[kk + t4 + 4][col];
            }
#pragma unroll
            for (int mf = 0; mf < 2; mf++)
#pragma unroll
                for (int nf = 0; nf < 4; nf++) mma_tf32(acc[mf][nf], a[mf], b[nf]);
        }
        __syncthreads();
        if (it + 1 < NIT) { store_s(); __syncthreads(); }
    }

    // epilogue: scaled atomic accumulation into y
#pragma unroll
    for (int mf = 0; mf < 2; mf++) {
        int r0 = wm * 32 + mf * 16 + g8;
        int r1 = r0 + 8;
        bool v0 = (m0 + r0) < cnt;
        bool v1 = (m0 + r1) < cnt;
        int   tok0 = v0 ? stok[r0] : 0;
        int   tok1 = v1 ? stok[r1] : 0;
        float wt0  = v0 ? swt[r0] : 0.f;
        float wt1  = v1 ? swt[r1] : 0.f;
#pragma unroll
        for (int nf = 0; nf < 4; nf++) {
            int cn = n0 + wn * 32 + nf * 8 + 2 * t4;
            if (v0) {
                atomicAdd(&y[(size_t)tok0 * HID + cn],     wt0 * acc[mf][nf][0]);
                atomicAdd(&y[(size_t)tok0 * HID + cn + 1], wt0 * acc[mf][nf][1]);
            }
            if (v1) {
                atomicAdd(&y[(size_t)tok1 * HID + cn],     wt1 * acc[mf][nf][2]);
                atomicAdd(&y[(size_t)tok1 * HID + cn + 1], wt1 * acc[mf][nf][3]);
            }
        }
    }
}

// ---------------- launch -----------------------------------------------------
extern "C" void kernel_launch(void* const* d_in, const int* in_sizes, int n_in,
                              void* d_out, int out_size) {
    const float* x    = (const float*)d_in[0];   // [2048,1024]
    const float* gw   = (const float*)d_in[1];   // [64,1024]
    const float* bias = (const float*)d_in[2];   // [64]
    const float* w13  = (const float*)d_in[3];   // [64,1024,1024]
    const float* w2   = (const float*)d_in[4];   // [64,1024,512]
    float* y = (float*)d_out;                    // [2048,1024]

    cudaMemsetAsync(y, 0, (size_t)TOKENS * HID * sizeof(float), 0);
    zero_cnt_kernel<<<1, 64>>>();
    router_kernel<<<TOKENS / 128, 128>>>(x, gw);
    topk_kernel<<<TOKENS / 256, 256>>>(bias);
    w13_mma_kernel<<<dim3(INTER / 64, TOKENS / 64, NEXP), 256>>>(x, w13);
    w2_mma_kernel<<<dim3(HID / 128, TOKENS / 64, NEXP), 256>>>(w2, y);
}

// round 4
// speedup vs baseline: 1.6711x; 1.2661x over previous
#include <cuda_runtime.h>
#include <math.h>
#include <stdint.h>

#define TOKENS 2048
#define HID    1024
#define NEXP   64
#define INTER  512
#define TOPK   8
#define NGRP   8
#define TOPKG  4

// dynamic smem layout (bytes)
#define SM_STOK 0
#define SM_SWT  512
#define SM_X    1024                   // 2 stages x 32x136 words x 4B = 17408 each
#define SM_W    (1024 + 2*17408)       // 35840
#define SM_TOT  (35840 + 2*17408)      // 70656
#define PITCH   136                    // words; 136 mod 32 == 8 -> conflict-free frags
#define STAGE_W 4352                   // 32*136 words per stage

// ---------------- scratch ----------------------------------------------------
__device__ float g_scores[TOKENS * NEXP];
__device__ int   g_cnt[NEXP];
__device__ int   g_tok[NEXP * TOKENS];
__device__ float g_wt[NEXP * TOKENS];
__device__ float g_h[(size_t)NEXP * TOKENS * INTER];

__global__ void zero_cnt_kernel() {
    if (threadIdx.x < NEXP) g_cnt[threadIdx.x] = 0;
}

// ---------------- helpers ----------------------------------------------------
__device__ __forceinline__ uint32_t f2tf32(float f) {
    uint32_t u;
    asm("cvt.rna.tf32.f32 %0, %1;" : "=r"(u) : "f"(f));
    return u;
}
__device__ __forceinline__ void mma_tf32(float c[4], const uint32_t a[4], const uint32_t b[2]) {
    asm volatile(
        "mma.sync.aligned.m16n8k8.row.col.f32.tf32.tf32.f32 "
        "{%0,%1,%2,%3},{%4,%5,%6,%7},{%8,%9},{%0,%1,%2,%3};"
        : "+f"(c[0]), "+f"(c[1]), "+f"(c[2]), "+f"(c[3])
        : "r"(a[0]), "r"(a[1]), "r"(a[2]), "r"(a[3]), "r"(b[0]), "r"(b[1]));
}
__device__ __forceinline__ float silu(float g) { return g / (1.f + expf(-g)); }
__device__ __forceinline__ void red_add_v2(float* p, float a, float b) {
    asm volatile("red.global.add.v2.f32 [%0], {%1,%2};" :: "l"(p), "f"(a), "f"(b) : "memory");
}

// ---------------- router: scores = sigmoid(x @ gate_w^T) ---------------------
__global__ __launch_bounds__(128) void router_kernel(const float* __restrict__ x,
                                                     const float* __restrict__ gw) {
    __shared__ float Xs[16][132];
    __shared__ float Gs[16][68];
    const int m0  = blockIdx.x * 128;
    const int tid = threadIdx.x;
    const int ty  = tid >> 3;
    const int tx  = tid & 7;

    float acc[8][8];
#pragma unroll
    for (int i = 0; i < 8; i++)
#pragma unroll
        for (int j = 0; j < 8; j++) acc[i][j] = 0.f;

    const float* xrow = x + (size_t)(m0 + tid) * HID;
    const float* grow = gw + (size_t)tid * HID;

    for (int k0 = 0; k0 < HID; k0 += 16) {
#pragma unroll
        for (int i = 0; i < 4; i++) {
            float4 v = *(const float4*)(xrow + k0 + i * 4);
            Xs[i * 4 + 0][tid] = v.x; Xs[i * 4 + 1][tid] = v.y;
            Xs[i * 4 + 2][tid] = v.z; Xs[i * 4 + 3][tid] = v.w;
        }
        if (tid < 64) {
#pragma unroll
            for (int i = 0; i < 4; i++) {
                float4 v = *(const float4*)(grow + k0 + i * 4);
                Gs[i * 4 + 0][tid] = v.x; Gs[i * 4 + 1][tid] = v.y;
                Gs[i * 4 + 2][tid] = v.z; Gs[i * 4 + 3][tid] = v.w;
            }
        }
        __syncthreads();
#pragma unroll
        for (int k = 0; k < 16; k++) {
            float a[8], b[8];
            *(float4*)(a)     = *(const float4*)&Xs[k][ty * 8];
            *(float4*)(a + 4) = *(const float4*)&Xs[k][ty * 8 + 4];
            *(float4*)(b)     = *(const float4*)&Gs[k][tx * 8];
            *(float4*)(b + 4) = *(const float4*)&Gs[k][tx * 8 + 4];
#pragma unroll
            for (int i = 0; i < 8; i++)
#pragma unroll
                for (int j = 0; j < 8; j++) acc[i][j] += a[i] * b[j];
        }
        __syncthreads();
    }

#pragma unroll
    for (int i = 0; i < 8; i++) {
        int t = m0 + ty * 8 + i;
#pragma unroll
        for (int j = 0; j < 8; j++) {
            g_scores[(size_t)t * NEXP + tx * 8 + j] = 1.f / (1.f + expf(-acc[i][j]));
        }
    }
}

// ---------------- grouped top-k routing (exact) ------------------------------
__global__ void topk_kernel(const float* __restrict__ bias) {
    int t = blockIdx.x * blockDim.x + threadIdx.x;
    if (t >= TOKENS) return;

    float sraw[NEXP], sb[NEXP];
    const float* sc = g_scores + (size_t)t * NEXP;
#pragma unroll
    for (int e = 0; e < NEXP; e++) { sraw[e] = sc[e]; sb[e] = sraw[e] + bias[e]; }

    float gs[NGRP];
#pragma unroll
    for (int g = 0; g < NGRP; g++) {
        float m1 = -1e30f, m2 = -1e30f;
#pragma unroll
        for (int j = 0; j < NEXP / NGRP; j++) {
            float v = sb[g * (NEXP / NGRP) + j];
            if (v > m1) { m2 = m1; m1 = v; } else if (v > m2) { m2 = v; }
        }
        gs[g] = m1 + m2;
    }

    unsigned gsel = 0;
    for (int it = 0; it < TOPKG; it++) {
        int best = -1; float bv = -1e30f;
#pragma unroll
        for (int g = 0; g < NGRP; g++)
            if (!((gsel >> g) & 1u) && gs[g] > bv) { bv = gs[g]; best = g; }
        gsel |= 1u << best;
    }

    unsigned long long esel = 0ull;
    int   ids[TOPK];
    float w[TOPK];
    float wsum = 0.f;
    for (int it = 0; it < TOPK; it++) {
        int best = -1; float bv = -1e30f;
#pragma unroll
        for (int e = 0; e < NEXP; e++) {
            if (((gsel >> (e >> 3)) & 1u) && !((esel >> e) & 1ull)) {
                float v = sb[e];
                if (v > bv) { bv = v; best = e; }
            }
        }
        esel |= 1ull << best;
        ids[it] = best;
        w[it]   = sraw[best];
        wsum   += sraw[best];
    }
    float inv = 1.f / wsum;

    for (int it = 0; it < TOPK; it++) {
        int e   = ids[it];
        int pos = atomicAdd(&g_cnt[e], 1);
        g_tok[e * TOKENS + pos] = t;
        g_wt[e * TOKENS + pos]  = w[it] * inv;
    }
}

// ---------------- expert GEMM1: h = silu(x@Wg^T)*(x@Wu^T) --------------------
// block 128 tokens x (64 gate + 64 up), BK=32, 256 thr, 8 warps (2m x 4n), warp 64x32
__global__ __launch_bounds__(256) void w13_k(const float* __restrict__ x,
                                             const float* __restrict__ w13) {
    extern __shared__ char smem[];
    int* stok = (int*)smem;
    uint32_t* Xb = (uint32_t*)(smem + SM_X);
    uint32_t* Wb = (uint32_t*)(smem + SM_W);

    const int e   = blockIdx.z;
    const int cnt = g_cnt[e];
    const int m0  = blockIdx.y * 128;
    if (m0 >= cnt) return;
    const int n0  = blockIdx.x * 64;

    const int tid = threadIdx.x, lane = tid & 31, wid = tid >> 5;
    const int wm = wid & 1, wn = wid >> 1, t4 = lane & 3, g8 = lane >> 2;

    if (tid < 128) stok[tid] = (m0 + tid < cnt) ? g_tok[e * TOKENS + m0 + tid] : -1;
    __syncthreads();

    // loader roles: each thread loads 64B of A and 64B of B per stage
    const int ra    = tid & 127;
    const int khalf = tid >> 7;            // 0/1 -> k 0..15 / 16..31
    const int tokr  = stok[ra];
    const float* arow = x + (size_t)(tokr >= 0 ? tokr : 0) * HID + khalf * 16;
    const int wr = (ra < 64) ? (n0 + ra) : (INTER + n0 + (ra - 64));
    const float* brow = w13 + (size_t)e * (2 * INTER) * HID + (size_t)wr * HID + khalf * 16;

    float4 av[4], bv[4];
    auto gload = [&](int k0) {
#pragma unroll
        for (int j = 0; j < 4; j++) {
            av[j] = (tokr >= 0) ? __ldg((const float4*)(arow + k0 + j * 4))
                                : make_float4(0.f, 0.f, 0.f, 0.f);
            bv[j] = __ldg((const float4*)(brow + k0 + j * 4));
        }
    };
    auto sstore = [&](int s) {
        uint32_t* Xs = Xb + s * STAGE_W;
        uint32_t* Ws = Wb + s * STAGE_W;
#pragma unroll
        for (int j = 0; j < 4; j++) {
            int kk = khalf * 16 + j * 4;
            Xs[(kk + 0) * PITCH + ra] = f2tf32(av[j].x);
            Xs[(kk + 1) * PITCH + ra] = f2tf32(av[j].y);
            Xs[(kk + 2) * PITCH + ra] = f2tf32(av[j].z);
            Xs[(kk + 3) * PITCH + ra] = f2tf32(av[j].w);
            Ws[(kk + 0) * PITCH + ra] = f2tf32(bv[j].x);
            Ws[(kk + 1) * PITCH + ra] = f2tf32(bv[j].y);
            Ws[(kk + 2) * PITCH + ra] = f2tf32(bv[j].z);
            Ws[(kk + 3) * PITCH + ra] = f2tf32(bv[j].w);
        }
    };

    float acc[4][4][4];
#pragma unroll
    for (int i = 0; i < 4; i++)
#pragma unroll
        for (int j = 0; j < 4; j++)
#pragma unroll
            for (int c = 0; c < 4; c++) acc[i][j][c] = 0.f;

    gload(0); sstore(0);
    __syncthreads();

    const int NIT = HID / 32;   // 32
    for (int it = 0; it < NIT; it++) {
        const int s = it & 1;
        if (it + 1 < NIT) gload((it + 1) * 32);

        const uint32_t* Xs = Xb + s * STAGE_W;
        const uint32_t* Ws = Wb + s * STAGE_W;
#pragma unroll
        for (int ks = 0; ks < 4; ks++) {
            const int kk = ks * 8;
            uint32_t a[4][4], b[4][2];
#pragma unroll
            for (int mf = 0; mf < 4; mf++) {
                int mrow = wm * 64 + mf * 16 + g8;
                a[mf][0] = Xs[(kk + t4) * PITCH + mrow];
                a[mf][1] = Xs[(kk + t4) * PITCH + mrow + 8];
                a[mf][2] = Xs[(kk + t4 + 4) * PITCH + mrow];
                a[mf][3] = Xs[(kk + t4 + 4) * PITCH + mrow + 8];
            }
#pragma unroll
            for (int nf = 0; nf < 4; nf++) {
                int col = ((nf < 2) ? (wn * 16 + nf * 8) : (64 + wn * 16 + (nf - 2) * 8)) + g8;
                b[nf][0] = Ws[(kk + t4) * PITCH + col];
                b[nf][1] = Ws[(kk + t4 + 4) * PITCH + col];
            }
#pragma unroll
            for (int mf = 0; mf < 4; mf++)
#pragma unroll
                for (int nf = 0; nf < 4; nf++) mma_tf32(acc[mf][nf], a[mf], b[nf]);
        }
        if (it + 1 < NIT) sstore(s ^ 1);
        __syncthreads();
    }

    // epilogue: SwiGLU fuse (nf 0,1 gate) with (nf 2,3 up)
#pragma unroll
    for (int mf = 0; mf < 4; mf++) {
        int r0 = wm * 64 + mf * 16 + g8;
        int r1 = r0 + 8;
#pragma unroll
        for (int nf = 0; nf < 2; nf++) {
            int c = n0 + wn * 16 + nf * 8 + t4 * 2;
            if (m0 + r0 < cnt) {
                float2 o;
                o.x = silu(acc[mf][nf][0]) * acc[mf][nf + 2][0];
                o.y = silu(acc[mf][nf][1]) * acc[mf][nf + 2][1];
                *(float2*)&g_h[((size_t)e * TOKENS + m0 + r0) * INTER + c] = o;
            }
            if (m0 + r1 < cnt) {
                float2 o;
                o.x = silu(acc[mf][nf][2]) * acc[mf][nf + 2][2];
                o.y = silu(acc[mf][nf][3]) * acc[mf][nf + 2][3];
                *(float2*)&g_h[((size_t)e * TOKENS + m0 + r1) * INTER + c] = o;
            }
        }
    }
}

// ---------------- expert GEMM2: y += wt * (h @ W2^T) -------------------------
// block 128 slots x 128 hid cols, BK=32, K=512, 256 thr, warp 64x32
__global__ __launch_bounds__(256) void w2_k(const float* __restrict__ w2,
                                            float* __restrict__ y) {
    extern __shared__ char smem[];
    int*   stok = (int*)smem;
    float* swt  = (float*)(smem + SM_SWT);
    uint32_t* Xb = (uint32_t*)(smem + SM_X);
    uint32_t* Wb = (uint32_t*)(smem + SM_W);

    const int e   = blockIdx.z;
    const int cnt = g_cnt[e];
    const int m0  = blockIdx.y * 128;
    if (m0 >= cnt) return;
    const int n0  = blockIdx.x * 128;

    const int tid = threadIdx.x, lane = tid & 31, wid = tid >> 5;
    const int wm = wid & 1, wn = wid >> 1, t4 = lane & 3, g8 = lane >> 2;

    if (tid < 128) {
        bool v = m0 + tid < cnt;
        stok[tid] = v ? g_tok[e * TOKENS + m0 + tid] : 0;
        swt[tid]  = v ? g_wt[e * TOKENS + m0 + tid] : 0.f;
    }
    __syncthreads();

    const int ra    = tid & 127;
    const int khalf = tid >> 7;
    const bool avalid = (m0 + ra) < cnt;
    const float* arow = g_h + ((size_t)e * TOKENS + m0 + ra) * INTER + khalf * 16;
    const float* brow = w2 + (size_t)e * HID * INTER + (size_t)(n0 + ra) * INTER + khalf * 16;

    float4 av[4], bv[4];
    auto gload = [&](int k0) {
#pragma unroll
        for (int j = 0; j < 4; j++) {
            av[j] = avalid ? __ldg((const float4*)(arow + k0 + j * 4))
                           : make_float4(0.f, 0.f, 0.f, 0.f);
            bv[j] = __ldg((const float4*)(brow + k0 + j * 4));
        }
    };
    auto sstore = [&](int s) {
        uint32_t* Xs = Xb + s * STAGE_W;
        uint32_t* Ws = Wb + s * STAGE_W;
#pragma unroll
        for (int j = 0; j < 4; j++) {
            int kk = khalf * 16 + j * 4;
            Xs[(kk + 0) * PITCH + ra] = f2tf32(av[j].x);
            Xs[(kk + 1) * PITCH + ra] = f2tf32(av[j].y);
            Xs[(kk + 2) * PITCH + ra] = f2tf32(av[j].z);
            Xs[(kk + 3) * PITCH + ra] = f2tf32(av[j].w);
            Ws[(kk + 0) * PITCH + ra] = f2tf32(bv[j].x);
            Ws[(kk + 1) * PITCH + ra] = f2tf32(bv[j].y);
            Ws[(kk + 2) * PITCH + ra] = f2tf32(bv[j].z);
            Ws[(kk + 3) * PITCH + ra] = f2tf32(bv[j].w);
        }
    };

    float acc[4][4][4];
#pragma unroll
    for (int i = 0; i < 4; i++)
#pragma unroll
        for (int j = 0; j < 4; j++)
#pragma unroll
            for (int c = 0; c < 4; c++) acc[i][j][c] = 0.f;

    gload(0); sstore(0);
    __syncthreads();

    const int NIT = INTER / 32;   // 16
    for (int it = 0; it < NIT; it++) {
        const int s = it & 1;
        if (it + 1 < NIT) gload((it + 1) * 32);

        const uint32_t* Xs = Xb + s * STAGE_W;
        const uint32_t* Ws = Wb + s * STAGE_W;
#pragma unroll
        for (int ks = 0; ks < 4; ks++) {
            const int kk = ks * 8;
            uint32_t a[4][4], b[4][2];
#pragma unroll
            for (int mf = 0; mf < 4; mf++) {
                int mrow = wm * 64 + mf * 16 + g8;
                a[mf][0] = Xs[(kk + t4) * PITCH + mrow];
                a[mf][1] = Xs[(kk + t4) * PITCH + mrow + 8];
                a[mf][2] = Xs[(kk + t4 + 4) * PITCH + mrow];
                a[mf][3] = Xs[(kk + t4 + 4) * PITCH + mrow + 8];
            }
#pragma unroll
            for (int nf = 0; nf < 4; nf++) {
                int col = wn * 32 + nf * 8 + g8;
                b[nf][0] = Ws[(kk + t4) * PITCH + col];
                b[nf][1] = Ws[(kk + t4 + 4) * PITCH + col];
            }
#pragma unroll
            for (int mf = 0; mf < 4; mf++)
#pragma unroll
                for (int nf = 0; nf < 4; nf++) mma_tf32(acc[mf][nf], a[mf], b[nf]);
        }
        if (it + 1 < NIT) sstore(s ^ 1);
        __syncthreads();
    }

    // epilogue: scaled reductions into y
#pragma unroll
    for (int mf = 0; mf < 4; mf++) {
        int r0 = wm * 64 + mf * 16 + g8;
        int r1 = r0 + 8;
        bool v0 = (m0 + r0) < cnt;
        bool v1 = (m0 + r1) < cnt;
        int   tok0 = stok[r0], tok1 = stok[r1];
        float wt0 = swt[r0],  wt1 = swt[r1];
#pragma unroll
        for (int nf = 0; nf < 4; nf++) {
            int c = n0 + wn * 32 + nf * 8 + t4 * 2;
            if (v0) red_add_v2(&y[(size_t)tok0 * HID + c],
                               wt0 * acc[mf][nf][0], wt0 * acc[mf][nf][1]);
            if (v1) red_add_v2(&y[(size_t)tok1 * HID + c],
                               wt1 * acc[mf][nf][2], wt1 * acc[mf][nf][3]);
        }
    }
}

// ---------------- launch ------------------------------------------------------
extern "C" void kernel_launch(void* const* d_in, const int* in_sizes, int n_in,
                              void* d_out, int out_size) {
    const float* x    = (const float*)d_in[0];   // [2048,1024]
    const float* gw   = (const float*)d_in[1];   // [64,1024]
    const float* bias = (const float*)d_in[2];   // [64]
    const float* w13  = (const float*)d_in[3];   // [64,1024,1024]
    const float* w2   = (const float*)d_in[4];   // [64,1024,512]
    float* y = (float*)d_out;                    // [2048,1024]

    cudaFuncSetAttribute(w13_k, cudaFuncAttributeMaxDynamicSharedMemorySize, SM_TOT);
    cudaFuncSetAttribute(w2_k,  cudaFuncAttributeMaxDynamicSharedMemorySize, SM_TOT);

    cudaMemsetAsync(y, 0, (size_t)TOKENS * HID * sizeof(float), 0);
    zero_cnt_kernel<<<1, 64>>>();
    router_kernel<<<TOKENS / 128, 128>>>(x, gw);
    topk_kernel<<<TOKENS / 256, 256>>>(bias);
    w13_k<<<dim3(INTER / 64, TOKENS / 128, NEXP), 256, SM_TOT>>>(x, w13);
    w2_k<<<dim3(HID / 128, TOKENS / 128, NEXP), 256, SM_TOT>>>(w2, y);
}

// round 5
// speedup vs baseline: 2.1487x; 1.2858x over previous
#include <cuda_runtime.h>
#include <cuda_fp16.h>
#include <math.h>
#include <stdint.h>

#define TOKENS 2048
#define HID    1024
#define NEXP   64
#define INTER  512
#define TOPK   8
#define NGRP   8
#define TOPKG  4

// smem word layout: w[kp][row], kp = k/2 (fp16 pair), PITCH words per kp-row
#define PITCH   136
#define STAGE_W (16 * PITCH)              // 16 kp-rows per BK=32 stage
#define SM_X    1024
#define SM_W    (1024 + 2 * STAGE_W * 4)  // 18432
#define SM_TOT  (SM_W + 2 * STAGE_W * 4)  // 35840

// ---------------- scratch ----------------------------------------------------
__device__ float  g_scores[TOKENS * NEXP];
__device__ int    g_cnt[NEXP];
__device__ int    g_tok[NEXP * TOKENS];
__device__ float  g_wt[NEXP * TOKENS];
__device__ __half g_h[(size_t)NEXP * TOKENS * INTER];   // fp16 SwiGLU output

__global__ void zero_cnt_kernel() {
    if (threadIdx.x < NEXP) g_cnt[threadIdx.x] = 0;
}

// ---------------- helpers ----------------------------------------------------
__device__ __forceinline__ uint32_t packh2(float a, float b) {
    __half2 h = __float22half2_rn(make_float2(a, b));
    return *(uint32_t*)&h;
}
__device__ __forceinline__ void mma_f16(float c[4], const uint32_t a[4], const uint32_t b[2]) {
    asm volatile(
        "mma.sync.aligned.m16n8k16.row.col.f32.f16.f16.f32 "
        "{%0,%1,%2,%3},{%4,%5,%6,%7},{%8,%9},{%0,%1,%2,%3};"
        : "+f"(c[0]), "+f"(c[1]), "+f"(c[2]), "+f"(c[3])
        : "r"(a[0]), "r"(a[1]), "r"(a[2]), "r"(a[3]), "r"(b[0]), "r"(b[1]));
}
__device__ __forceinline__ float silu(float g) { return g / (1.f + expf(-g)); }
__device__ __forceinline__ void red_add_v2(float* p, float a, float b) {
    asm volatile("red.global.add.v2.f32 [%0], {%1,%2};" :: "l"(p), "f"(a), "f"(b) : "memory");
}

// ---------------- router: scores = sigmoid(x @ gate_w^T) ---------------------
__global__ __launch_bounds__(128) void router_kernel(const float* __restrict__ x,
                                                     const float* __restrict__ gw) {
    __shared__ float Xs[16][132];
    __shared__ float Gs[16][68];
    const int m0  = blockIdx.x * 128;
    const int tid = threadIdx.x;
    const int ty  = tid >> 3;
    const int tx  = tid & 7;

    float acc[8][8];
#pragma unroll
    for (int i = 0; i < 8; i++)
#pragma unroll
        for (int j = 0; j < 8; j++) acc[i][j] = 0.f;

    const float* xrow = x + (size_t)(m0 + tid) * HID;
    const float* grow = gw + (size_t)tid * HID;

    for (int k0 = 0; k0 < HID; k0 += 16) {
#pragma unroll
        for (int i = 0; i < 4; i++) {
            float4 v = *(const float4*)(xrow + k0 + i * 4);
            Xs[i * 4 + 0][tid] = v.x; Xs[i * 4 + 1][tid] = v.y;
            Xs[i * 4 + 2][tid] = v.z; Xs[i * 4 + 3][tid] = v.w;
        }
        if (tid < 64) {
#pragma unroll
            for (int i = 0; i < 4; i++) {
                float4 v = *(const float4*)(grow + k0 + i * 4);
                Gs[i * 4 + 0][tid] = v.x; Gs[i * 4 + 1][tid] = v.y;
                Gs[i * 4 + 2][tid] = v.z; Gs[i * 4 + 3][tid] = v.w;
            }
        }
        __syncthreads();
#pragma unroll
        for (int k = 0; k < 16; k++) {
            float a[8], b[8];
            *(float4*)(a)     = *(const float4*)&Xs[k][ty * 8];
            *(float4*)(a + 4) = *(const float4*)&Xs[k][ty * 8 + 4];
            *(float4*)(b)     = *(const float4*)&Gs[k][tx * 8];
            *(float4*)(b + 4) = *(const float4*)&Gs[k][tx * 8 + 4];
#pragma unroll
            for (int i = 0; i < 8; i++)
#pragma unroll
                for (int j = 0; j < 8; j++) acc[i][j] += a[i] * b[j];
        }
        __syncthreads();
    }

#pragma unroll
    for (int i = 0; i < 8; i++) {
        int t = m0 + ty * 8 + i;
#pragma unroll
        for (int j = 0; j < 8; j++) {
            g_scores[(size_t)t * NEXP + tx * 8 + j] = 1.f / (1.f + expf(-acc[i][j]));
        }
    }
}

// ---------------- grouped top-k routing (exact) ------------------------------
__global__ void topk_kernel(const float* __restrict__ bias) {
    int t = blockIdx.x * blockDim.x + threadIdx.x;
    if (t >= TOKENS) return;

    float sraw[NEXP], sb[NEXP];
    const float* sc = g_scores + (size_t)t * NEXP;
#pragma unroll
    for (int e = 0; e < NEXP; e++) { sraw[e] = sc[e]; sb[e] = sraw[e] + bias[e]; }

    float gs[NGRP];
#pragma unroll
    for (int g = 0; g < NGRP; g++) {
        float m1 = -1e30f, m2 = -1e30f;
#pragma unroll
        for (int j = 0; j < NEXP / NGRP; j++) {
            float v = sb[g * (NEXP / NGRP) + j];
            if (v > m1) { m2 = m1; m1 = v; } else if (v > m2) { m2 = v; }
        }
        gs[g] = m1 + m2;
    }

    unsigned gsel = 0;
    for (int it = 0; it < TOPKG; it++) {
        int best = -1; float bv = -1e30f;
#pragma unroll
        for (int g = 0; g < NGRP; g++)
            if (!((gsel >> g) & 1u) && gs[g] > bv) { bv = gs[g]; best = g; }
        gsel |= 1u << best;
    }

    unsigned long long esel = 0ull;
    int   ids[TOPK];
    float w[TOPK];
    float wsum = 0.f;
    for (int it = 0; it < TOPK; it++) {
        int best = -1; float bv = -1e30f;
#pragma unroll
        for (int e = 0; e < NEXP; e++) {
            if (((gsel >> (e >> 3)) & 1u) && !((esel >> e) & 1ull)) {
                float v = sb[e];
                if (v > bv) { bv = v; best = e; }
            }
        }
        esel |= 1ull << best;
        ids[it] = best;
        w[it]   = sraw[best];
        wsum   += sraw[best];
    }
    float inv = 1.f / wsum;

    for (int it = 0; it < TOPK; it++) {
        int e   = ids[it];
        int pos = atomicAdd(&g_cnt[e], 1);
        g_tok[e * TOKENS + pos] = t;
        g_wt[e * TOKENS + pos]  = w[it] * inv;
    }
}

// ---------------- expert GEMM1 (fp16 mma): h = silu(x@Wg^T)*(x@Wu^T) ---------
// block 128 tokens x (64 gate + 64 up), BK=32, 256 thr, 8 warps (2m x 4n)
__global__ __launch_bounds__(256) void w13_k(const float* __restrict__ x,
                                             const float* __restrict__ w13) {
    extern __shared__ char smem[];
    int* stok = (int*)smem;
    uint32_t* Xb = (uint32_t*)(smem + SM_X);
    uint32_t* Wb = (uint32_t*)(smem + SM_W);

    const int e   = blockIdx.z;
    const int cnt = g_cnt[e];
    const int m0  = blockIdx.y * 128;
    if (m0 >= cnt) return;
    const int n0  = blockIdx.x * 64;

    const int tid = threadIdx.x, lane = tid & 31, wid = tid >> 5;
    const int wm = wid & 1, wn = wid >> 1, t4 = lane & 3, g8 = lane >> 2;

    if (tid < 128) stok[tid] = (m0 + tid < cnt) ? g_tok[e * TOKENS + m0 + tid] : -1;
    __syncthreads();

    const int ra    = tid & 127;
    const int khalf = tid >> 7;            // 0/1 -> k 0..15 / 16..31
    const int tokr  = stok[ra];
    const float* arow = x + (size_t)(tokr >= 0 ? tokr : 0) * HID + khalf * 16;
    const int wr = (ra < 64) ? (n0 + ra) : (INTER + n0 + (ra - 64));
    const float* brow = w13 + (size_t)e * (2 * INTER) * HID + (size_t)wr * HID + khalf * 16;

    float4 av[4], bv[4];
    auto gload = [&](int k0) {
#pragma unroll
        for (int j = 0; j < 4; j++) {
            av[j] = (tokr >= 0) ? __ldg((const float4*)(arow + k0 + j * 4))
                                : make_float4(0.f, 0.f, 0.f, 0.f);
            bv[j] = __ldg((const float4*)(brow + k0 + j * 4));
        }
    };
    auto sstore = [&](int s) {
        uint32_t* Xs = Xb + s * STAGE_W;
        uint32_t* Ws = Wb + s * STAGE_W;
#pragma unroll
        for (int j = 0; j < 4; j++) {
            int kp = khalf * 8 + j * 2;
            Xs[(kp + 0) * PITCH + ra] = packh2(av[j].x, av[j].y);
            Xs[(kp + 1) * PITCH + ra] = packh2(av[j].z, av[j].w);
            Ws[(kp + 0) * PITCH + ra] = packh2(bv[j].x, bv[j].y);
            Ws[(kp + 1) * PITCH + ra] = packh2(bv[j].z, bv[j].w);
        }
    };

    float acc[4][4][4];
#pragma unroll
    for (int i = 0; i < 4; i++)
#pragma unroll
        for (int j = 0; j < 4; j++)
#pragma unroll
            for (int c = 0; c < 4; c++) acc[i][j][c] = 0.f;

    gload(0); sstore(0);
    __syncthreads();

    const int NIT = HID / 32;   // 32
    for (int it = 0; it < NIT; it++) {
        const int s = it & 1;
        if (it + 1 < NIT) gload((it + 1) * 32);

        const uint32_t* Xs = Xb + s * STAGE_W;
        const uint32_t* Ws = Wb + s * STAGE_W;
#pragma unroll
        for (int ks = 0; ks < 2; ks++) {        // two k16 steps per BK=32
            const int kk = ks * 8;              // kp offset
            uint32_t a[4][4], b[4][2];
#pragma unroll
            for (int mf = 0; mf < 4; mf++) {
                int mrow = wm * 64 + mf * 16 + g8;
                a[mf][0] = Xs[(kk + t4) * PITCH + mrow];
                a[mf][1] = Xs[(kk + t4) * PITCH + mrow + 8];
                a[mf][2] = Xs[(kk + 4 + t4) * PITCH + mrow];
                a[mf][3] = Xs[(kk + 4 + t4) * PITCH + mrow + 8];
            }
#pragma unroll
            for (int nf = 0; nf < 4; nf++) {
                int col = ((nf < 2) ? (wn * 16 + nf * 8) : (64 + wn * 16 + (nf - 2) * 8)) + g8;
                b[nf][0] = Ws[(kk + t4) * PITCH + col];
                b[nf][1] = Ws[(kk + 4 + t4) * PITCH + col];
            }
#pragma unroll
            for (int mf = 0; mf < 4; mf++)
#pragma unroll
                for (int nf = 0; nf < 4; nf++) mma_f16(acc[mf][nf], a[mf], b[nf]);
        }
        if (it + 1 < NIT) sstore(s ^ 1);
        __syncthreads();
    }

    // epilogue: SwiGLU fuse (nf 0,1 gate) with (nf 2,3 up) -> fp16 g_h
#pragma unroll
    for (int mf = 0; mf < 4; mf++) {
        int r0 = wm * 64 + mf * 16 + g8;
        int r1 = r0 + 8;
#pragma unroll
        for (int nf = 0; nf < 2; nf++) {
            int c = n0 + wn * 16 + nf * 8 + t4 * 2;
            if (m0 + r0 < cnt) {
                uint32_t o = packh2(silu(acc[mf][nf][0]) * acc[mf][nf + 2][0],
                                    silu(acc[mf][nf][1]) * acc[mf][nf + 2][1]);
                *(uint32_t*)&g_h[((size_t)e * TOKENS + m0 + r0) * INTER + c] = o;
            }
            if (m0 + r1 < cnt) {
                uint32_t o = packh2(silu(acc[mf][nf][2]) * acc[mf][nf + 2][2],
                                    silu(acc[mf][nf][3]) * acc[mf][nf + 2][3]);
                *(uint32_t*)&g_h[((size_t)e * TOKENS + m0 + r1) * INTER + c] = o;
            }
        }
    }
}

// ---------------- expert GEMM2 (fp16 mma): y += wt * (h @ W2^T) --------------
// block 128 slots x 128 hid cols, BK=32, K=512, 256 thr
__global__ __launch_bounds__(256) void w2_k(const float* __restrict__ w2,
                                            float* __restrict__ y) {
    extern __shared__ char smem[];
    int*   stok = (int*)smem;
    float* swt  = (float*)(smem + 512);
    uint32_t* Xb = (uint32_t*)(smem + SM_X);
    uint32_t* Wb = (uint32_t*)(smem + SM_W);

    const int e   = blockIdx.z;
    const int cnt = g_cnt[e];
    const int m0  = blockIdx.y * 128;
    if (m0 >= cnt) return;
    const int n0  = blockIdx.x * 128;

    const int tid = threadIdx.x, lane = tid & 31, wid = tid >> 5;
    const int wm = wid & 1, wn = wid >> 1, t4 = lane & 3, g8 = lane >> 2;

    if (tid < 128) {
        bool v = m0 + tid < cnt;
        stok[tid] = v ? g_tok[e * TOKENS + m0 + tid] : 0;
        swt[tid]  = v ? g_wt[e * TOKENS + m0 + tid] : 0.f;
    }
    __syncthreads();

    const int ra    = tid & 127;
    const int khalf = tid >> 7;
    const bool avalid = (m0 + ra) < cnt;
    const __half* arow = g_h + ((size_t)e * TOKENS + m0 + ra) * INTER + khalf * 16;
    const float*  brow = w2 + (size_t)e * HID * INTER + (size_t)(n0 + ra) * INTER + khalf * 16;

    uint4  ah[2];          // 16 fp16 = 8 words
    float4 bv[4];
    auto gload = [&](int k0) {
        if (avalid) {
            ah[0] = __ldg((const uint4*)(arow + k0));
            ah[1] = __ldg((const uint4*)(arow + k0 + 8));
        } else {
            ah[0] = make_uint4(0, 0, 0, 0); ah[1] = ah[0];
        }
#pragma unroll
        for (int j = 0; j < 4; j++)
            bv[j] = __ldg((const float4*)(brow + k0 + j * 4));
    };
    auto sstore = [&](int s) {
        uint32_t* Xs = Xb + s * STAGE_W;
        uint32_t* Ws = Wb + s * STAGE_W;
        const uint32_t* aw = (const uint32_t*)ah;
#pragma unroll
        for (int q = 0; q < 8; q++)
            Xs[(khalf * 8 + q) * PITCH + ra] = aw[q];
#pragma unroll
        for (int j = 0; j < 4; j++) {
            int kp = khalf * 8 + j * 2;
            Ws[(kp + 0) * PITCH + ra] = packh2(bv[j].x, bv[j].y);
            Ws[(kp + 1) * PITCH + ra] = packh2(bv[j].z, bv[j].w);
        }
    };

    float acc[4][4][4];
#pragma unroll
    for (int i = 0; i < 4; i++)
#pragma unroll
        for (int j = 0; j < 4; j++)
#pragma unroll
            for (int c = 0; c < 4; c++) acc[i][j][c] = 0.f;

    gload(0); sstore(0);
    __syncthreads();

    const int NIT = INTER / 32;   // 16
    for (int it = 0; it < NIT; it++) {
        const int s = it & 1;
        if (it + 1 < NIT) gload((it + 1) * 32);

        const uint32_t* Xs = Xb + s * STAGE_W;
        const uint32_t* Ws = Wb + s * STAGE_W;
#pragma unroll
        for (int ks = 0; ks < 2; ks++) {
            const int kk = ks * 8;
            uint32_t a[4][4], b[4][2];
#pragma unroll
            for (int mf = 0; mf < 4; mf++) {
                int mrow = wm * 64 + mf * 16 + g8;
                a[mf][0] = Xs[(kk + t4) * PITCH + mrow];
                a[mf][1] = Xs[(kk + t4) * PITCH + mrow + 8];
                a[mf][2] = Xs[(kk + 4 + t4) * PITCH + mrow];
                a[mf][3] = Xs[(kk + 4 + t4) * PITCH + mrow + 8];
            }
#pragma unroll
            for (int nf = 0; nf < 4; nf++) {
                int col = wn * 32 + nf * 8 + g8;
                b[nf][0] = Ws[(kk + t4) * PITCH + col];
                b[nf][1] = Ws[(kk + 4 + t4) * PITCH + col];
            }
#pragma unroll
            for (int mf = 0; mf < 4; mf++)
#pragma unroll
                for (int nf = 0; nf < 4; nf++) mma_f16(acc[mf][nf], a[mf], b[nf]);
        }
        if (it + 1 < NIT) sstore(s ^ 1);
        __syncthreads();
    }

    // epilogue: scaled reductions into y
#pragma unroll
    for (int mf = 0; mf < 4; mf++) {
        int r0 = wm * 64 + mf * 16 + g8;
        int r1 = r0 + 8;
        bool v0 = (m0 + r0) < cnt;
        bool v1 = (m0 + r1) < cnt;
        int   tok0 = stok[r0], tok1 = stok[r1];
        float wt0 = swt[r0],  wt1 = swt[r1];
#pragma unroll
        for (int nf = 0; nf < 4; nf++) {
            int c = n0 + wn * 32 + nf * 8 + t4 * 2;
            if (v0) red_add_v2(&y[(size_t)tok0 * HID + c],
                               wt0 * acc[mf][nf][0], wt0 * acc[mf][nf][1]);
            if (v1) red_add_v2(&y[(size_t)tok1 * HID + c],
                               wt1 * acc[mf][nf][2], wt1 * acc[mf][nf][3]);
        }
    }
}

// ---------------- launch ------------------------------------------------------
extern "C" void kernel_launch(void* const* d_in, const int* in_sizes, int n_in,
                              void* d_out, int out_size) {
    const float* x    = (const float*)d_in[0];   // [2048,1024]
    const float* gw   = (const float*)d_in[1];   // [64,1024]
    const float* bias = (const float*)d_in[2];   // [64]
    const float* w13  = (const float*)d_in[3];   // [64,1024,1024]
    const float* w2   = (const float*)d_in[4];   // [64,1024,512]
    float* y = (float*)d_out;                    // [2048,1024]

    cudaFuncSetAttribute(w13_k, cudaFuncAttributeMaxDynamicSharedMemorySize, SM_TOT);
    cudaFuncSetAttribute(w2_k,  cudaFuncAttributeMaxDynamicSharedMemorySize, SM_TOT);

    cudaMemsetAsync(y, 0, (size_t)TOKENS * HID * sizeof(float), 0);
    zero_cnt_kernel<<<1, 64>>>();
    router_kernel<<<TOKENS / 128, 128>>>(x, gw);
    topk_kernel<<<TOKENS / 256, 256>>>(bias);
    w13_k<<<dim3(INTER / 64, TOKENS / 128, NEXP), 256, SM_TOT>>>(x, w13);
    w2_k<<<dim3(HID / 128, TOKENS / 128, NEXP), 256, SM_TOT>>>(w2, y);
}

// round 6
// speedup vs baseline: 3.2767x; 1.5250x over previous
#include <cuda_runtime.h>
#include <cuda_fp16.h>
#include <math.h>
#include <stdint.h>

#define TOKENS 2048
#define HID    1024
#define NEXP   64
#define INTER  512
#define TOPK   8
#define NGRP   8
#define TOPKG  4

// smem: [row][kp] row-major fp16-pairs, PITCH2=20 words/row (16 data + 4 pad)
// bank math: 20*r mod 32 spans {0,4,8,...,28} for r in 0..7 -> conflict-free
// ldmatrix phases and near-optimal STS.
#define PITCH2  20
#define ROWB    80                       // bytes per row
#define STG     10240                    // 128 rows * 80B per stage
#define SA_OFF  1024
#define SB_OFF  (1024 + 2 * STG)         // 21504
#define SM_TOT  (SB_OFF + 2 * STG)       // 41984

// ---------------- scratch ----------------------------------------------------
__device__ float  g_scores[TOKENS * NEXP];
__device__ int    g_cnt[NEXP];
__device__ int    g_tok[NEXP * TOKENS];
__device__ float  g_wt[NEXP * TOKENS];
__device__ __half g_h[(size_t)NEXP * TOKENS * INTER];

__global__ void zero_cnt_kernel() {
    if (threadIdx.x < NEXP) g_cnt[threadIdx.x] = 0;
}

// ---------------- helpers ----------------------------------------------------
__device__ __forceinline__ uint32_t smem_u32(const void* p) {
    uint32_t a;
    asm("{ .reg .u64 t; cvta.to.shared.u64 t, %1; cvt.u32.u64 %0, t; }" : "=r"(a) : "l"(p));
    return a;
}
__device__ __forceinline__ uint32_t packh2(float a, float b) {
    __half2 h = __float22half2_rn(make_float2(a, b));
    return *(uint32_t*)&h;
}
__device__ __forceinline__ void ldsm_x4(uint32_t r[4], uint32_t addr) {
    asm volatile("ldmatrix.sync.aligned.m8n8.x4.shared.b16 {%0,%1,%2,%3}, [%4];"
                 : "=r"(r[0]), "=r"(r[1]), "=r"(r[2]), "=r"(r[3]) : "r"(addr));
}
__device__ __forceinline__ void mma_f16(float c[4], const uint32_t a[4],
                                        uint32_t b0, uint32_t b1) {
    asm volatile(
        "mma.sync.aligned.m16n8k16.row.col.f32.f16.f16.f32 "
        "{%0,%1,%2,%3},{%4,%5,%6,%7},{%8,%9},{%0,%1,%2,%3};"
        : "+f"(c[0]), "+f"(c[1]), "+f"(c[2]), "+f"(c[3])
        : "r"(a[0]), "r"(a[1]), "r"(a[2]), "r"(a[3]), "r"(b0), "r"(b1));
}
__device__ __forceinline__ float silu(float g) { return g / (1.f + expf(-g)); }
__device__ __forceinline__ void red_add_v2(float* p, float a, float b) {
    asm volatile("red.global.add.v2.f32 [%0], {%1,%2};" :: "l"(p), "f"(a), "f"(b) : "memory");
}

// ---------------- router: scores = sigmoid(x @ gate_w^T) ---------------------
__global__ __launch_bounds__(128) void router_kernel(const float* __restrict__ x,
                                                     const float* __restrict__ gw) {
    __shared__ float Xs[16][132];
    __shared__ float Gs[16][68];
    const int m0  = blockIdx.x * 128;
    const int tid = threadIdx.x;
    const int ty  = tid >> 3;
    const int tx  = tid & 7;

    float acc[8][8];
#pragma unroll
    for (int i = 0; i < 8; i++)
#pragma unroll
        for (int j = 0; j < 8; j++) acc[i][j] = 0.f;

    const float* xrow = x + (size_t)(m0 + tid) * HID;
    const float* grow = gw + (size_t)tid * HID;

    for (int k0 = 0; k0 < HID; k0 += 16) {
#pragma unroll
        for (int i = 0; i < 4; i++) {
            float4 v = *(const float4*)(xrow + k0 + i * 4);
            Xs[i * 4 + 0][tid] = v.x; Xs[i * 4 + 1][tid] = v.y;
            Xs[i * 4 + 2][tid] = v.z; Xs[i * 4 + 3][tid] = v.w;
        }
        if (tid < 64) {
#pragma unroll
            for (int i = 0; i < 4; i++) {
                float4 v = *(const float4*)(grow + k0 + i * 4);
                Gs[i * 4 + 0][tid] = v.x; Gs[i * 4 + 1][tid] = v.y;
                Gs[i * 4 + 2][tid] = v.z; Gs[i * 4 + 3][tid] = v.w;
            }
        }
        __syncthreads();
#pragma unroll
        for (int k = 0; k < 16; k++) {
            float a[8], b[8];
            *(float4*)(a)     = *(const float4*)&Xs[k][ty * 8];
            *(float4*)(a + 4) = *(const float4*)&Xs[k][ty * 8 + 4];
            *(float4*)(b)     = *(const float4*)&Gs[k][tx * 8];
            *(float4*)(b + 4) = *(const float4*)&Gs[k][tx * 8 + 4];
#pragma unroll
            for (int i = 0; i < 8; i++)
#pragma unroll
                for (int j = 0; j < 8; j++) acc[i][j] += a[i] * b[j];
        }
        __syncthreads();
    }

#pragma unroll
    for (int i = 0; i < 8; i++) {
        int t = m0 + ty * 8 + i;
#pragma unroll
        for (int j = 0; j < 8; j++) {
            g_scores[(size_t)t * NEXP + tx * 8 + j] = 1.f / (1.f + expf(-acc[i][j]));
        }
    }
}

// ---------------- grouped top-k routing (exact) ------------------------------
__global__ void topk_kernel(const float* __restrict__ bias) {
    int t = blockIdx.x * blockDim.x + threadIdx.x;
    if (t >= TOKENS) return;

    float sraw[NEXP], sb[NEXP];
    const float* sc = g_scores + (size_t)t * NEXP;
#pragma unroll
    for (int e = 0; e < NEXP; e++) { sraw[e] = sc[e]; sb[e] = sraw[e] + bias[e]; }

    float gs[NGRP];
#pragma unroll
    for (int g = 0; g < NGRP; g++) {
        float m1 = -1e30f, m2 = -1e30f;
#pragma unroll
        for (int j = 0; j < NEXP / NGRP; j++) {
            float v = sb[g * (NEXP / NGRP) + j];
            if (v > m1) { m2 = m1; m1 = v; } else if (v > m2) { m2 = v; }
        }
        gs[g] = m1 + m2;
    }

    unsigned gsel = 0;
    for (int it = 0; it < TOPKG; it++) {
        int best = -1; float bv = -1e30f;
#pragma unroll
        for (int g = 0; g < NGRP; g++)
            if (!((gsel >> g) & 1u) && gs[g] > bv) { bv = gs[g]; best = g; }
        gsel |= 1u << best;
    }

    unsigned long long esel = 0ull;
    int   ids[TOPK];
    float w[TOPK];
    float wsum = 0.f;
    for (int it = 0; it < TOPK; it++) {
        int best = -1; float bv = -1e30f;
#pragma unroll
        for (int e = 0; e < NEXP; e++) {
            if (((gsel >> (e >> 3)) & 1u) && !((esel >> e) & 1ull)) {
                float v = sb[e];
                if (v > bv) { bv = v; best = e; }
            }
        }
        esel |= 1ull << best;
        ids[it] = best;
        w[it]   = sraw[best];
        wsum   += sraw[best];
    }
    float inv = 1.f / wsum;

    for (int it = 0; it < TOPK; it++) {
        int e   = ids[it];
        int pos = atomicAdd(&g_cnt[e], 1);
        g_tok[e * TOKENS + pos] = t;
        g_wt[e * TOKENS + pos]  = w[it] * inv;
    }
}

// ---------------- expert GEMM1 (fp16 mma + ldmatrix): h = swiglu -------------
// block 128 tokens x (64 gate + 64 up), BK=32, 256 thr, 8 warps 64x32
__global__ __launch_bounds__(256, 2) void w13_k(const float* __restrict__ x,
                                                const float* __restrict__ w13) {
    extern __shared__ char smem[];
    int* stok = (int*)smem;

    const int e   = blockIdx.z;
    const int cnt = g_cnt[e];
    const int m0  = blockIdx.y * 128;
    if (m0 >= cnt) return;
    const int n0  = blockIdx.x * 64;

    const int tid = threadIdx.x, lane = tid & 31, wid = tid >> 5;
    const int wm = wid & 1, wn = wid >> 1, t4 = lane & 3, g8 = lane >> 2;

    if (tid < 128) stok[tid] = (m0 + tid < cnt) ? g_tok[e * TOKENS + m0 + tid] : -1;
    __syncthreads();

    const uint32_t sbase = smem_u32(smem);

    // ---- coalesced loaders: 8 lanes cover one 128B row segment ----
    const int lrow = tid >> 3;          // 0..31
    const int lc   = tid & 7;           // 16B chunk within row
    const float* aptr[4]; bool aval[4]; uint32_t ast[4];
    const float* bptr[4];               uint32_t bst[4];
    const float* w13e = w13 + (size_t)e * (2 * INTER) * HID;
#pragma unroll
    for (int p = 0; p < 4; p++) {
        int r = lrow + 32 * p;
        int tk = stok[r];
        aval[p] = tk >= 0;
        aptr[p] = x + (size_t)(tk >= 0 ? tk : 0) * HID + lc * 4;
        ast[p]  = r * ROWB + lc * 8;
        int bw = (r < 64) ? (n0 + r) : (INTER + n0 + (r - 64));
        bptr[p] = w13e + (size_t)bw * HID + lc * 4;
        bst[p]  = r * ROWB + lc * 8;
    }

    uint2 apk[4], bpk[4];
    auto gload = [&](int k0) {
#pragma unroll
        for (int p = 0; p < 4; p++) {
            float4 v = aval[p] ? __ldg((const float4*)(aptr[p] + k0))
                               : make_float4(0.f, 0.f, 0.f, 0.f);
            apk[p] = make_uint2(packh2(v.x, v.y), packh2(v.z, v.w));
            float4 w = __ldg((const float4*)(bptr[p] + k0));
            bpk[p] = make_uint2(packh2(w.x, w.y), packh2(w.z, w.w));
        }
    };
    auto sstore = [&](int s) {
#pragma unroll
        for (int p = 0; p < 4; p++) {
            *(uint2*)(smem + SA_OFF + s * STG + ast[p]) = apk[p];
            *(uint2*)(smem + SB_OFF + s * STG + bst[p]) = bpk[p];
        }
    };

    // ---- ldmatrix base addresses ----
    const int lr  = ((lane >> 3) & 1) * 8 + (lane & 7);
    const int lkb = (lane >> 4) * 16;
    const uint32_t aAddr = sbase + SA_OFF + (wm * 64 + lr) * ROWB + lkb;
    const uint32_t bAddr = sbase + SB_OFF + (wn * 16 + lr) * ROWB + lkb;

    float acc[4][4][4];
#pragma unroll
    for (int i = 0; i < 4; i++)
#pragma unroll
        for (int j = 0; j < 4; j++)
#pragma unroll
            for (int c = 0; c < 4; c++) acc[i][j][c] = 0.f;

    gload(0); sstore(0);
    __syncthreads();

    const int NIT = HID / 32;
    for (int it = 0; it < NIT; it++) {
        const int s = it & 1;
        if (it + 1 < NIT) gload((it + 1) * 32);
        const uint32_t sOff = s * STG;
#pragma unroll
        for (int ks = 0; ks < 2; ks++) {
            uint32_t a[4][4], bg[4], bu[4];
#pragma unroll
            for (int mf = 0; mf < 4; mf++)
                ldsm_x4(a[mf], aAddr + sOff + mf * 16 * ROWB + ks * 32);
            ldsm_x4(bg, bAddr + sOff + ks * 32);              // gate cols
            ldsm_x4(bu, bAddr + sOff + 64 * ROWB + ks * 32);  // up cols
#pragma unroll
            for (int mf = 0; mf < 4; mf++) {
                mma_f16(acc[mf][0], a[mf], bg[0], bg[2]);
                mma_f16(acc[mf][1], a[mf], bg[1], bg[3]);
                mma_f16(acc[mf][2], a[mf], bu[0], bu[2]);
                mma_f16(acc[mf][3], a[mf], bu[1], bu[3]);
            }
        }
        if (it + 1 < NIT) sstore(s ^ 1);
        __syncthreads();
    }

    // epilogue: SwiGLU fuse gate (nf 0,1) with up (nf 2,3) -> fp16 g_h
#pragma unroll
    for (int mf = 0; mf < 4; mf++) {
        int r0 = wm * 64 + mf * 16 + g8;
        int r1 = r0 + 8;
#pragma unroll
        for (int nf = 0; nf < 2; nf++) {
            int c = n0 + wn * 16 + nf * 8 + t4 * 2;
            if (m0 + r0 < cnt) {
                uint32_t o = packh2(silu(acc[mf][nf][0]) * acc[mf][nf + 2][0],
                                    silu(acc[mf][nf][1]) * acc[mf][nf + 2][1]);
                *(uint32_t*)&g_h[((size_t)e * TOKENS + m0 + r0) * INTER + c] = o;
            }
            if (m0 + r1 < cnt) {
                uint32_t o = packh2(silu(acc[mf][nf][2]) * acc[mf][nf + 2][2],
                                    silu(acc[mf][nf][3]) * acc[mf][nf + 2][3]);
                *(uint32_t*)&g_h[((size_t)e * TOKENS + m0 + r1) * INTER + c] = o;
            }
        }
    }
}

// ---------------- expert GEMM2 (fp16 mma + ldmatrix): y += wt * (h @ W2^T) ---
// block 128 slots x 128 hid cols, BK=32, K=512
__global__ __launch_bounds__(256, 2) void w2_k(const float* __restrict__ w2,
                                               float* __restrict__ y) {
    extern __shared__ char smem[];
    int*   stok = (int*)smem;
    float* swt  = (float*)(smem + 512);

    const int e   = blockIdx.z;
    const int cnt = g_cnt[e];
    const int m0  = blockIdx.y * 128;
    if (m0 >= cnt) return;
    const int n0  = blockIdx.x * 128;

    const int tid = threadIdx.x, lane = tid & 31, wid = tid >> 5;
    const int wm = wid & 1, wn = wid >> 1, t4 = lane & 3, g8 = lane >> 2;

    if (tid < 128) {
        bool v = m0 + tid < cnt;
        stok[tid] = v ? g_tok[e * TOKENS + m0 + tid] : 0;
        swt[tid]  = v ? g_wt[e * TOKENS + m0 + tid] : 0.f;
    }
    __syncthreads();

    const uint32_t sbase = smem_u32(smem);

    // A loader: fp16 rows from g_h, 4 lanes cover one 64B row (no CVT)
    const int arow_ = tid >> 2;         // 0..63
    const int ac    = tid & 3;          // 16B chunk (8 halves)
    const __half* aptr[2]; bool aval[2]; uint32_t ast[2];
#pragma unroll
    for (int p = 0; p < 2; p++) {
        int r = arow_ + 64 * p;
        aval[p] = (m0 + r) < cnt;
        aptr[p] = g_h + ((size_t)e * TOKENS + m0 + r) * INTER + ac * 8;
        ast[p]  = r * ROWB + ac * 16;
    }
    // B loader: fp32 weight rows, 8 lanes per 128B row
    const int lrow = tid >> 3;
    const int lc   = tid & 7;
    const float* bptr[4]; uint32_t bst[4];
    const float* w2e = w2 + (size_t)e * HID * INTER;
#pragma unroll
    for (int p = 0; p < 4; p++) {
        int r = lrow + 32 * p;
        bptr[p] = w2e + (size_t)(n0 + r) * INTER + lc * 4;
        bst[p]  = r * ROWB + lc * 8;
    }

    uint4 araw[2]; uint2 bpk[4];
    auto gload = [&](int k0) {
#pragma unroll
        for (int p = 0; p < 2; p++)
            araw[p] = aval[p] ? __ldg((const uint4*)(aptr[p] + k0))
                              : make_uint4(0, 0, 0, 0);
#pragma unroll
        for (int p = 0; p < 4; p++) {
            float4 w = __ldg((const float4*)(bptr[p] + k0));
            bpk[p] = make_uint2(packh2(w.x, w.y), packh2(w.z, w.w));
        }
    };
    auto sstore = [&](int s) {
#pragma unroll
        for (int p = 0; p < 2; p++)
            *(uint4*)(smem + SA_OFF + s * STG + ast[p]) = araw[p];
#pragma unroll
        for (int p = 0; p < 4; p++)
            *(uint2*)(smem + SB_OFF + s * STG + bst[p]) = bpk[p];
    };

    const int lr  = ((lane >> 3) & 1) * 8 + (lane & 7);
    const int lkb = (lane >> 4) * 16;
    const uint32_t aAddr = sbase + SA_OFF + (wm * 64 + lr) * ROWB + lkb;
    const uint32_t bAddr = sbase + SB_OFF + (wn * 32 + lr) * ROWB + lkb;

    float acc[4][4][4];
#pragma unroll
    for (int i = 0; i < 4; i++)
#pragma unroll
        for (int j = 0; j < 4; j++)
#pragma unroll
            for (int c = 0; c < 4; c++) acc[i][j][c] = 0.f;

    gload(0); sstore(0);
    __syncthreads();

    const int NIT = INTER / 32;
    for (int it = 0; it < NIT; it++) {
        const int s = it & 1;
        if (it + 1 < NIT) gload((it + 1) * 32);
        const uint32_t sOff = s * STG;
#pragma unroll
        for (int ks = 0; ks < 2; ks++) {
            uint32_t a[4][4], b0[4], b1[4];
#pragma unroll
            for (int mf = 0; mf < 4; mf++)
                ldsm_x4(a[mf], aAddr + sOff + mf * 16 * ROWB + ks * 32);
            ldsm_x4(b0, bAddr + sOff + ks * 32);              // cols 0-15
            ldsm_x4(b1, bAddr + sOff + 16 * ROWB + ks * 32);  // cols 16-31
#pragma unroll
            for (int mf = 0; mf < 4; mf++) {
                mma_f16(acc[mf][0], a[mf], b0[0], b0[2]);
                mma_f16(acc[mf][1], a[mf], b0[1], b0[3]);
                mma_f16(acc[mf][2], a[mf], b1[0], b1[2]);
                mma_f16(acc[mf][3], a[mf], b1[1], b1[3]);
            }
        }
        if (it + 1 < NIT) sstore(s ^ 1);
        __syncthreads();
    }

    // epilogue: scaled reductions into y
#pragma unroll
    for (int mf = 0; mf < 4; mf++) {
        int r0 = wm * 64 + mf * 16 + g8;
        int r1 = r0 + 8;
        bool v0 = (m0 + r0) < cnt;
        bool v1 = (m0 + r1) < cnt;
        int   tok0 = stok[r0], tok1 = stok[r1];
        float wt0 = swt[r0],  wt1 = swt[r1];
#pragma unroll
        for (int nf = 0; nf < 4; nf++) {
            int c = n0 + wn * 32 + nf * 8 + t4 * 2;
            if (v0) red_add_v2(&y[(size_t)tok0 * HID + c],
                               wt0 * acc[mf][nf][0], wt0 * acc[mf][nf][1]);
            if (v1) red_add_v2(&y[(size_t)tok1 * HID + c],
                               wt1 * acc[mf][nf][2], wt1 * acc[mf][nf][3]);
        }
    }
}

// ---------------- launch ------------------------------------------------------
extern "C" void kernel_launch(void* const* d_in, const int* in_sizes, int n_in,
                              void* d_out, int out_size) {
    const float* x    = (const float*)d_in[0];   // [2048,1024]
    const float* gw   = (const float*)d_in[1];   // [64,1024]
    const float* bias = (const float*)d_in[2];   // [64]
    const float* w13  = (const float*)d_in[3];   // [64,1024,1024]
    const float* w2   = (const float*)d_in[4];   // [64,1024,512]
    float* y = (float*)d_out;                    // [2048,1024]

    cudaFuncSetAttribute(w13_k, cudaFuncAttributeMaxDynamicSharedMemorySize, SM_TOT);
    cudaFuncSetAttribute(w2_k,  cudaFuncAttributeMaxDynamicSharedMemorySize, SM_TOT);

    cudaMemsetAsync(y, 0, (size_t)TOKENS * HID * sizeof(float), 0);
    zero_cnt_kernel<<<1, 64>>>();
    router_kernel<<<TOKENS / 128, 128>>>(x, gw);
    topk_kernel<<<TOKENS / 256, 256>>>(bias);
    w13_k<<<dim3(INTER / 64, TOKENS / 128, NEXP), 256, SM_TOT>>>(x, w13);
    w2_k<<<dim3(HID / 128, TOKENS / 128, NEXP), 256, SM_TOT>>>(w2, y);
}

// round 7
// speedup vs baseline: 3.5122x; 1.0719x over previous
#include <cuda_runtime.h>
#include <cuda_fp16.h>
#include <math.h>
#include <stdint.h>

#define TOKENS 2048
#define HID    1024
#define NEXP   64
#define INTER  512
#define TOPK   8
#define NGRP   8
#define TOPKG  4

// smem: [row][k] fp16, 64B data + 16B pad per row (BK=32) -> conflict-free
// ldmatrix (20*r mod 32 spans 0,20,8,28,16,4,24,12) per R6-proven math.
#define ROWB    80
#define STG     10240                    // 128 rows * 80B per stage
#define NSTAGE  4
#define SA_OFF  1024
#define SB_OFF  (SA_OFF + NSTAGE * STG)  // 41984
#define SM_TOT  (SB_OFF + NSTAGE * STG)  // 82944

// ---------------- scratch ----------------------------------------------------
__device__ float  g_scores[TOKENS * NEXP];
__device__ int    g_cnt[NEXP];
__device__ int    g_tok[NEXP * TOKENS];
__device__ float  g_wt[NEXP * TOKENS];
__device__ __half g_h[(size_t)NEXP * TOKENS * INTER];
__device__ __half g_w13h[(size_t)NEXP * 2 * INTER * HID];   // 128 MB
__device__ __half g_w2h[(size_t)NEXP * HID * INTER];        // 64 MB
__device__ __half g_xh[TOKENS * HID];                       // 4 MB

__global__ void zero_cnt_kernel() {
    if (threadIdx.x < NEXP) g_cnt[threadIdx.x] = 0;
}

// ---------------- helpers ----------------------------------------------------
__device__ __forceinline__ uint32_t smem_u32(const void* p) {
    uint32_t a;
    asm("{ .reg .u64 t; cvta.to.shared.u64 t, %1; cvt.u32.u64 %0, t; }" : "=r"(a) : "l"(p));
    return a;
}
__device__ __forceinline__ uint32_t packh2(float a, float b) {
    __half2 h = __float22half2_rn(make_float2(a, b));
    return *(uint32_t*)&h;
}
__device__ __forceinline__ void cpa16(uint32_t dst, const void* src, uint32_t nbytes) {
    asm volatile("cp.async.cg.shared.global [%0], [%1], 16, %2;"
                 :: "r"(dst), "l"(src), "r"(nbytes) : "memory");
}
#define CP_COMMIT() asm volatile("cp.async.commit_group;" ::: "memory")
#define CP_WAIT2()  asm volatile("cp.async.wait_group 2;" ::: "memory")
__device__ __forceinline__ void ldsm_x4(uint32_t r[4], uint32_t addr) {
    asm volatile("ldmatrix.sync.aligned.m8n8.x4.shared.b16 {%0,%1,%2,%3}, [%4];"
                 : "=r"(r[0]), "=r"(r[1]), "=r"(r[2]), "=r"(r[3]) : "r"(addr));
}
__device__ __forceinline__ void mma_f16(float c[4], const uint32_t a[4],
                                        uint32_t b0, uint32_t b1) {
    asm volatile(
        "mma.sync.aligned.m16n8k16.row.col.f32.f16.f16.f32 "
        "{%0,%1,%2,%3},{%4,%5,%6,%7},{%8,%9},{%0,%1,%2,%3};"
        : "+f"(c[0]), "+f"(c[1]), "+f"(c[2]), "+f"(c[3])
        : "r"(a[0]), "r"(a[1]), "r"(a[2]), "r"(a[3]), "r"(b0), "r"(b1));
}
__device__ __forceinline__ float silu(float g) { return g / (1.f + expf(-g)); }
__device__ __forceinline__ void red_add_v2(float* p, float a, float b) {
    asm volatile("red.global.add.v2.f32 [%0], {%1,%2};" :: "l"(p), "f"(a), "f"(b) : "memory");
}

// ---------------- fp32 -> fp16 streaming conversion --------------------------
__global__ __launch_bounds__(256) void conv_kernel(const float4* __restrict__ src,
                                                   uint4* __restrict__ dst) {
    int i = blockIdx.x * blockDim.x + threadIdx.x;   // one uint4 (8 halves) out
    float4 a = __ldg(&src[2 * i]);
    float4 b = __ldg(&src[2 * i + 1]);
    uint4 o;
    o.x = packh2(a.x, a.y); o.y = packh2(a.z, a.w);
    o.z = packh2(b.x, b.y); o.w = packh2(b.z, b.w);
    dst[i] = o;
}

// ---------------- router: scores = sigmoid(x @ gate_w^T) ---------------------
__global__ __launch_bounds__(128) void router_kernel(const float* __restrict__ x,
                                                     const float* __restrict__ gw) {
    __shared__ float Xs[16][132];
    __shared__ float Gs[16][68];
    const int m0  = blockIdx.x * 128;
    const int tid = threadIdx.x;
    const int ty  = tid >> 3;
    const int tx  = tid & 7;

    float acc[8][8];
#pragma unroll
    for (int i = 0; i < 8; i++)
#pragma unroll
        for (int j = 0; j < 8; j++) acc[i][j] = 0.f;

    const float* xrow = x + (size_t)(m0 + tid) * HID;
    const float* grow = gw + (size_t)tid * HID;

    for (int k0 = 0; k0 < HID; k0 += 16) {
#pragma unroll
        for (int i = 0; i < 4; i++) {
            float4 v = *(const float4*)(xrow + k0 + i * 4);
            Xs[i * 4 + 0][tid] = v.x; Xs[i * 4 + 1][tid] = v.y;
            Xs[i * 4 + 2][tid] = v.z; Xs[i * 4 + 3][tid] = v.w;
        }
        if (tid < 64) {
#pragma unroll
            for (int i = 0; i < 4; i++) {
                float4 v = *(const float4*)(grow + k0 + i * 4);
                Gs[i * 4 + 0][tid] = v.x; Gs[i * 4 + 1][tid] = v.y;
                Gs[i * 4 + 2][tid] = v.z; Gs[i * 4 + 3][tid] = v.w;
            }
        }
        __syncthreads();
#pragma unroll
        for (int k = 0; k < 16; k++) {
            float a[8], b[8];
            *(float4*)(a)     = *(const float4*)&Xs[k][ty * 8];
            *(float4*)(a + 4) = *(const float4*)&Xs[k][ty * 8 + 4];
            *(float4*)(b)     = *(const float4*)&Gs[k][tx * 8];
            *(float4*)(b + 4) = *(const float4*)&Gs[k][tx * 8 + 4];
#pragma unroll
            for (int i = 0; i < 8; i++)
#pragma unroll
                for (int j = 0; j < 8; j++) acc[i][j] += a[i] * b[j];
        }
        __syncthreads();
    }

#pragma unroll
    for (int i = 0; i < 8; i++) {
        int t = m0 + ty * 8 + i;
#pragma unroll
        for (int j = 0; j < 8; j++) {
            g_scores[(size_t)t * NEXP + tx * 8 + j] = 1.f / (1.f + expf(-acc[i][j]));
        }
    }
}

// ---------------- grouped top-k routing (exact) ------------------------------
__global__ void topk_kernel(const float* __restrict__ bias) {
    int t = blockIdx.x * blockDim.x + threadIdx.x;
    if (t >= TOKENS) return;

    float sraw[NEXP], sb[NEXP];
    const float* sc = g_scores + (size_t)t * NEXP;
#pragma unroll
    for (int e = 0; e < NEXP; e++) { sraw[e] = sc[e]; sb[e] = sraw[e] + bias[e]; }

    float gs[NGRP];
#pragma unroll
    for (int g = 0; g < NGRP; g++) {
        float m1 = -1e30f, m2 = -1e30f;
#pragma unroll
        for (int j = 0; j < NEXP / NGRP; j++) {
            float v = sb[g * (NEXP / NGRP) + j];
            if (v > m1) { m2 = m1; m1 = v; } else if (v > m2) { m2 = v; }
        }
        gs[g] = m1 + m2;
    }

    unsigned gsel = 0;
    for (int it = 0; it < TOPKG; it++) {
        int best = -1; float bv = -1e30f;
#pragma unroll
        for (int g = 0; g < NGRP; g++)
            if (!((gsel >> g) & 1u) && gs[g] > bv) { bv = gs[g]; best = g; }
        gsel |= 1u << best;
    }

    unsigned long long esel = 0ull;
    int   ids[TOPK];
    float w[TOPK];
    float wsum = 0.f;
    for (int it = 0; it < TOPK; it++) {
        int best = -1; float bv = -1e30f;
#pragma unroll
        for (int e = 0; e < NEXP; e++) {
            if (((gsel >> (e >> 3)) & 1u) && !((esel >> e) & 1ull)) {
                float v = sb[e];
                if (v > bv) { bv = v; best = e; }
            }
        }
        esel |= 1ull << best;
        ids[it] = best;
        w[it]   = sraw[best];
        wsum   += sraw[best];
    }
    float inv = 1.f / wsum;

    for (int it = 0; it < TOPK; it++) {
        int e   = ids[it];
        int pos = atomicAdd(&g_cnt[e], 1);
        g_tok[e * TOKENS + pos] = t;
        g_wt[e * TOKENS + pos]  = w[it] * inv;
    }
}

// ---------------- expert GEMM1 (fp16, cp.async 4-stage): h = swiglu ----------
// block 128 tokens x (64 gate + 64 up), BK=32, 256 thr, 8 warps 64x32
__global__ __launch_bounds__(256, 2) void w13_k() {
    extern __shared__ char smem[];
    int* stok = (int*)smem;

    const int e   = blockIdx.z;
    const int cnt = g_cnt[e];
    const int m0  = blockIdx.y * 128;
    if (m0 >= cnt) return;
    const int n0  = blockIdx.x * 64;

    const int tid = threadIdx.x, lane = tid & 31, wid = tid >> 5;
    const int wm = wid & 1, wn = wid >> 1, t4 = lane & 3, g8 = lane >> 2;

    if (tid < 128) stok[tid] = (m0 + tid < cnt) ? g_tok[e * TOKENS + m0 + tid] : -1;
    __syncthreads();

    const uint32_t sbase = smem_u32(smem);

    // loader: 2 A chunks + 2 B chunks of 16B per thread per stage
    const __half* asrc[2]; uint32_t asz[2], aoff[2];
    const __half* bsrc[2]; uint32_t boff[2];
    const __half* w13e = g_w13h + (size_t)e * (2 * INTER) * HID;
#pragma unroll
    for (int p = 0; p < 2; p++) {
        int q   = tid + p * 256;
        int row = q >> 2, c = q & 3;
        int tk  = stok[row];
        asrc[p] = g_xh + (size_t)(tk >= 0 ? tk : 0) * HID + c * 8;
        asz[p]  = (tk >= 0) ? 16u : 0u;
        aoff[p] = row * ROWB + c * 16;
        int bw  = (row < 64) ? (n0 + row) : (INTER + n0 + (row - 64));
        bsrc[p] = w13e + (size_t)bw * HID + c * 8;
        boff[p] = row * ROWB + c * 16;
    }
    auto load_stage = [&](int s, int k0) {
#pragma unroll
        for (int p = 0; p < 2; p++) {
            cpa16(sbase + SA_OFF + s * STG + aoff[p], asrc[p] + k0, asz[p]);
            cpa16(sbase + SB_OFF + s * STG + boff[p], bsrc[p] + k0, 16u);
        }
    };

    const int lr  = ((lane >> 3) & 1) * 8 + (lane & 7);
    const int lkb = (lane >> 4) * 16;
    const uint32_t aAddr = sbase + SA_OFF + (wm * 64 + lr) * ROWB + lkb;
    const uint32_t bAddr = sbase + SB_OFF + (wn * 16 + lr) * ROWB + lkb;

    float acc[4][4][4];
#pragma unroll
    for (int i = 0; i < 4; i++)
#pragma unroll
        for (int j = 0; j < 4; j++)
#pragma unroll
            for (int c = 0; c < 4; c++) acc[i][j][c] = 0.f;

    // prologue: stages 0..2
#pragma unroll
    for (int s = 0; s < 3; s++) { load_stage(s, s * 32); CP_COMMIT(); }

    const int NIT = HID / 32;   // 32
    for (int it = 0; it < NIT; it++) {
        const int s = it & 3;
        CP_WAIT2();
        __syncthreads();
        if (it + 3 < NIT) load_stage((it + 3) & 3, (it + 3) * 32);
        CP_COMMIT();

        const uint32_t sOff = s * STG;
#pragma unroll
        for (int ks = 0; ks < 2; ks++) {
            uint32_t a[4][4], bg[4], bu[4];
#pragma unroll
            for (int mf = 0; mf < 4; mf++)
                ldsm_x4(a[mf], aAddr + sOff + mf * 16 * ROWB + ks * 32);
            ldsm_x4(bg, bAddr + sOff + ks * 32);              // gate cols
            ldsm_x4(bu, bAddr + sOff + 64 * ROWB + ks * 32);  // up cols
#pragma unroll
            for (int mf = 0; mf < 4; mf++) {
                mma_f16(acc[mf][0], a[mf], bg[0], bg[2]);
                mma_f16(acc[mf][1], a[mf], bg[1], bg[3]);
                mma_f16(acc[mf][2], a[mf], bu[0], bu[2]);
                mma_f16(acc[mf][3], a[mf], bu[1], bu[3]);
            }
        }
        __syncthreads();   // stage s fully consumed before refill in it+1
    }

    // epilogue: SwiGLU fuse gate (nf 0,1) with up (nf 2,3) -> fp16 g_h
#pragma unroll
    for (int mf = 0; mf < 4; mf++) {
        int r0 = wm * 64 + mf * 16 + g8;
        int r1 = r0 + 8;
#pragma unroll
        for (int nf = 0; nf < 2; nf++) {
            int c = n0 + wn * 16 + nf * 8 + t4 * 2;
            if (m0 + r0 < cnt) {
                uint32_t o = packh2(silu(acc[mf][nf][0]) * acc[mf][nf + 2][0],
                                    silu(acc[mf][nf][1]) * acc[mf][nf + 2][1]);
                *(uint32_t*)&g_h[((size_t)e * TOKENS + m0 + r0) * INTER + c] = o;
            }
            if (m0 + r1 < cnt) {
                uint32_t o = packh2(silu(acc[mf][nf][2]) * acc[mf][nf + 2][2],
                                    silu(acc[mf][nf][3]) * acc[mf][nf + 2][3]);
                *(uint32_t*)&g_h[((size_t)e * TOKENS + m0 + r1) * INTER + c] = o;
            }
        }
    }
}

// ---------------- expert GEMM2 (fp16, cp.async 4-stage): y += wt*(h@W2^T) ----
// block 128 slots x 128 hid cols, BK=32, K=512
__global__ __launch_bounds__(256, 2) void w2_k(float* __restrict__ y) {
    extern __shared__ char smem[];
    int*   stok = (int*)smem;
    float* swt  = (float*)(smem + 512);

    const int e   = blockIdx.z;
    const int cnt = g_cnt[e];
    const int m0  = blockIdx.y * 128;
    if (m0 >= cnt) return;
    const int n0  = blockIdx.x * 128;

    const int tid = threadIdx.x, lane = tid & 31, wid = tid >> 5;
    const int wm = wid & 1, wn = wid >> 1, t4 = lane & 3, g8 = lane >> 2;

    if (tid < 128) {
        bool v = m0 + tid < cnt;
        stok[tid] = v ? g_tok[e * TOKENS + m0 + tid] : 0;
        swt[tid]  = v ? g_wt[e * TOKENS + m0 + tid] : 0.f;
    }
    __syncthreads();

    const uint32_t sbase = smem_u32(smem);

    const __half* asrc[2]; uint32_t asz[2], aoff[2];
    const __half* bsrc[2]; uint32_t boff[2];
    const __half* w2e = g_w2h + (size_t)e * HID * INTER;
#pragma unroll
    for (int p = 0; p < 2; p++) {
        int q   = tid + p * 256;
        int row = q >> 2, c = q & 3;
        bool v  = (m0 + row) < cnt;
        asrc[p] = g_h + ((size_t)e * TOKENS + m0 + row) * INTER + c * 8;
        asz[p]  = v ? 16u : 0u;
        aoff[p] = row * ROWB + c * 16;
        bsrc[p] = w2e + (size_t)(n0 + row) * INTER + c * 8;
        boff[p] = row * ROWB + c * 16;
    }
    auto load_stage = [&](int s, int k0) {
#pragma unroll
        for (int p = 0; p < 2; p++) {
            cpa16(sbase + SA_OFF + s * STG + aoff[p], asrc[p] + k0, asz[p]);
            cpa16(sbase + SB_OFF + s * STG + boff[p], bsrc[p] + k0, 16u);
        }
    };

    const int lr  = ((lane >> 3) & 1) * 8 + (lane & 7);
    const int lkb = (lane >> 4) * 16;
    const uint32_t aAddr = sbase + SA_OFF + (wm * 64 + lr) * ROWB + lkb;
    const uint32_t bAddr = sbase + SB_OFF + (wn * 32 + lr) * ROWB + lkb;

    float acc[4][4][4];
#pragma unroll
    for (int i = 0; i < 4; i++)
#pragma unroll
        for (int j = 0; j < 4; j++)
#pragma unroll
            for (int c = 0; c < 4; c++) acc[i][j][c] = 0.f;

#pragma unroll
    for (int s = 0; s < 3; s++) { load_stage(s, s * 32); CP_COMMIT(); }

    const int NIT = INTER / 32;   // 16
    for (int it = 0; it < NIT; it++) {
        const int s = it & 3;
        CP_WAIT2();
        __syncthreads();
        if (it + 3 < NIT) load_stage((it + 3) & 3, (it + 3) * 32);
        CP_COMMIT();

        const uint32_t sOff = s * STG;
#pragma unroll
        for (int ks = 0; ks < 2; ks++) {
            uint32_t a[4][4], b0[4], b1[4];
#pragma unroll
            for (int mf = 0; mf < 4; mf++)
                ldsm_x4(a[mf], aAddr + sOff + mf * 16 * ROWB + ks * 32);
            ldsm_x4(b0, bAddr + sOff + ks * 32);              // cols 0-15
            ldsm_x4(b1, bAddr + sOff + 16 * ROWB + ks * 32);  // cols 16-31
#pragma unroll
            for (int mf = 0; mf < 4; mf++) {
                mma_f16(acc[mf][0], a[mf], b0[0], b0[2]);
                mma_f16(acc[mf][1], a[mf], b0[1], b0[3]);
                mma_f16(acc[mf][2], a[mf], b1[0], b1[2]);
                mma_f16(acc[mf][3], a[mf], b1[1], b1[3]);
            }
        }
        __syncthreads();
    }

    // epilogue: scaled reductions into y
#pragma unroll
    for (int mf = 0; mf < 4; mf++) {
        int r0 = wm * 64 + mf * 16 + g8;
        int r1 = r0 + 8;
        bool v0 = (m0 + r0) < cnt;
        bool v1 = (m0 + r1) < cnt;
        int   tok0 = stok[r0], tok1 = stok[r1];
        float wt0 = swt[r0],  wt1 = swt[r1];
#pragma unroll
        for (int nf = 0; nf < 4; nf++) {
            int c = n0 + wn * 32 + nf * 8 + t4 * 2;
            if (v0) red_add_v2(&y[(size_t)tok0 * HID + c],
                               wt0 * acc[mf][nf][0], wt0 * acc[mf][nf][1]);
            if (v1) red_add_v2(&y[(size_t)tok1 * HID + c],
                               wt1 * acc[mf][nf][2], wt1 * acc[mf][nf][3]);
        }
    }
}

// ---------------- launch ------------------------------------------------------
extern "C" void kernel_launch(void* const* d_in, const int* in_sizes, int n_in,
                              void* d_out, int out_size) {
    const float* x    = (const float*)d_in[0];   // [2048,1024]
    const float* gw   = (const float*)d_in[1];   // [64,1024]
    const float* bias = (const float*)d_in[2];   // [64]
    const float* w13  = (const float*)d_in[3];   // [64,1024,1024]
    const float* w2   = (const float*)d_in[4];   // [64,1024,512]
    float* y = (float*)d_out;                    // [2048,1024]

    cudaFuncSetAttribute(w13_k, cudaFuncAttributeMaxDynamicSharedMemorySize, SM_TOT);
    cudaFuncSetAttribute(w2_k,  cudaFuncAttributeMaxDynamicSharedMemorySize, SM_TOT);

    __half *d_w13h, *d_w2h, *d_xh;
    cudaGetSymbolAddress((void**)&d_w13h, g_w13h);
    cudaGetSymbolAddress((void**)&d_w2h,  g_w2h);
    cudaGetSymbolAddress((void**)&d_xh,   g_xh);

    cudaMemsetAsync(y, 0, (size_t)TOKENS * HID * sizeof(float), 0);
    zero_cnt_kernel<<<1, 64>>>();
    conv_kernel<<<(NEXP * 2 * INTER * HID / 8) / 256, 256>>>((const float4*)w13, (uint4*)d_w13h);
    conv_kernel<<<(NEXP * HID * INTER / 8) / 256, 256>>>((const float4*)w2, (uint4*)d_w2h);
    conv_kernel<<<(TOKENS * HID / 8) / 256, 256>>>((const float4*)x, (uint4*)d_xh);
    router_kernel<<<TOKENS / 128, 128>>>(x, gw);
    topk_kernel<<<TOKENS / 256, 256>>>(bias);
    w13_k<<<dim3(INTER / 64, TOKENS / 128, NEXP), 256, SM_TOT>>>();
    w2_k<<<dim3(HID / 128, TOKENS / 128, NEXP), 256, SM_TOT>>>(y);
}

// round 8
// speedup vs baseline: 3.5301x; 1.0051x over previous
#include <cuda_runtime.h>
#include <cuda_fp16.h>
#include <math.h>
#include <stdint.h>

#define TOKENS 2048
#define HID    1024
#define NEXP   64
#define INTER  512
#define TOPK   8
#define NGRP   8
#define TOPKG  4

// smem: [row][k] fp16, BK=64 -> 128B data + 16B pad per row.
// 144*r mod 128 spans {0,16,...,112} -> conflict-free ldmatrix phases.
#define ROWB    144
#define STG     18432                    // 128 rows * 144B per stage
#define NSTAGE  3
#define SA_OFF  1024
#define SB_OFF  (SA_OFF + NSTAGE * STG)  // 56320
#define SM_TOT  (SB_OFF + NSTAGE * STG)  // 111616

// ---------------- scratch ----------------------------------------------------
__device__ float  g_scores[TOKENS * NEXP];
__device__ int    g_cnt[NEXP];
__device__ int    g_tok[NEXP * TOKENS];
__device__ float  g_wt[NEXP * TOKENS];
__device__ __half g_h[(size_t)NEXP * TOKENS * INTER];
__device__ __half g_w13h[(size_t)NEXP * 2 * INTER * HID];   // 128 MB
__device__ __half g_w2h[(size_t)NEXP * HID * INTER];        // 64 MB
__device__ __half g_xh[TOKENS * HID];                       // 4 MB

__global__ void zero_cnt_kernel() {
    if (threadIdx.x < NEXP) g_cnt[threadIdx.x] = 0;
}

// ---------------- helpers ----------------------------------------------------
__device__ __forceinline__ uint32_t smem_u32(const void* p) {
    uint32_t a;
    asm("{ .reg .u64 t; cvta.to.shared.u64 t, %1; cvt.u32.u64 %0, t; }" : "=r"(a) : "l"(p));
    return a;
}
__device__ __forceinline__ uint32_t packh2(float a, float b) {
    __half2 h = __float22half2_rn(make_float2(a, b));
    return *(uint32_t*)&h;
}
__device__ __forceinline__ void cpa16(uint32_t dst, const void* src, uint32_t nbytes) {
    asm volatile("cp.async.cg.shared.global [%0], [%1], 16, %2;"
                 :: "r"(dst), "l"(src), "r"(nbytes) : "memory");
}
#define CP_COMMIT() asm volatile("cp.async.commit_group;" ::: "memory")
#define CP_WAIT1()  asm volatile("cp.async.wait_group 1;" ::: "memory")
__device__ __forceinline__ void ldsm_x4(uint32_t r[4], uint32_t addr) {
    asm volatile("ldmatrix.sync.aligned.m8n8.x4.shared.b16 {%0,%1,%2,%3}, [%4];"
                 : "=r"(r[0]), "=r"(r[1]), "=r"(r[2]), "=r"(r[3]) : "r"(addr));
}
__device__ __forceinline__ void mma_f16(float c[4], const uint32_t a[4],
                                        uint32_t b0, uint32_t b1) {
    asm volatile(
        "mma.sync.aligned.m16n8k16.row.col.f32.f16.f16.f32 "
        "{%0,%1,%2,%3},{%4,%5,%6,%7},{%8,%9},{%0,%1,%2,%3};"
        : "+f"(c[0]), "+f"(c[1]), "+f"(c[2]), "+f"(c[3])
        : "r"(a[0]), "r"(a[1]), "r"(a[2]), "r"(a[3]), "r"(b0), "r"(b1));
}
__device__ __forceinline__ float silu(float g) { return g / (1.f + expf(-g)); }
__device__ __forceinline__ void red_add_v2(float* p, float a, float b) {
    asm volatile("red.global.add.v2.f32 [%0], {%1,%2};" :: "l"(p), "f"(a), "f"(b) : "memory");
}

// ---------------- fp32 -> fp16 streaming conversion --------------------------
__global__ __launch_bounds__(256) void conv_kernel(const float4* __restrict__ src,
                                                   uint4* __restrict__ dst, int n4) {
    int i = blockIdx.x * blockDim.x + threadIdx.x;
    int stride = gridDim.x * blockDim.x;
    for (; i < n4; i += stride) {
        float4 a = __ldg(&src[2 * i]);
        float4 b = __ldg(&src[2 * i + 1]);
        uint4 o;
        o.x = packh2(a.x, a.y); o.y = packh2(a.z, a.w);
        o.z = packh2(b.x, b.y); o.w = packh2(b.z, b.w);
        dst[i] = o;
    }
}

// ---------------- router: scores = sigmoid(x @ gate_w^T) ---------------------
__global__ __launch_bounds__(128) void router_kernel(const float* __restrict__ x,
                                                     const float* __restrict__ gw) {
    __shared__ float Xs[16][132];
    __shared__ float Gs[16][68];
    const int m0  = blockIdx.x * 128;
    const int tid = threadIdx.x;
    const int ty  = tid >> 3;
    const int tx  = tid & 7;

    float acc[8][8];
#pragma unroll
    for (int i = 0; i < 8; i++)
#pragma unroll
        for (int j = 0; j < 8; j++) acc[i][j] = 0.f;

    const float* xrow = x + (size_t)(m0 + tid) * HID;
    const float* grow = gw + (size_t)tid * HID;

    for (int k0 = 0; k0 < HID; k0 += 16) {
#pragma unroll
        for (int i = 0; i < 4; i++) {
            float4 v = *(const float4*)(xrow + k0 + i * 4);
            Xs[i * 4 + 0][tid] = v.x; Xs[i * 4 + 1][tid] = v.y;
            Xs[i * 4 + 2][tid] = v.z; Xs[i * 4 + 3][tid] = v.w;
        }
        if (tid < 64) {
#pragma unroll
            for (int i = 0; i < 4; i++) {
                float4 v = *(const float4*)(grow + k0 + i * 4);
                Gs[i * 4 + 0][tid] = v.x; Gs[i * 4 + 1][tid] = v.y;
                Gs[i * 4 + 2][tid] = v.z; Gs[i * 4 + 3][tid] = v.w;
            }
        }
        __syncthreads();
#pragma unroll
        for (int k = 0; k < 16; k++) {
            float a[8], b[8];
            *(float4*)(a)     = *(const float4*)&Xs[k][ty * 8];
            *(float4*)(a + 4) = *(const float4*)&Xs[k][ty * 8 + 4];
            *(float4*)(b)     = *(const float4*)&Gs[k][tx * 8];
            *(float4*)(b + 4) = *(const float4*)&Gs[k][tx * 8 + 4];
#pragma unroll
            for (int i = 0; i < 8; i++)
#pragma unroll
                for (int j = 0; j < 8; j++) acc[i][j] += a[i] * b[j];
        }
        __syncthreads();
    }

#pragma unroll
    for (int i = 0; i < 8; i++) {
        int t = m0 + ty * 8 + i;
#pragma unroll
        for (int j = 0; j < 8; j++) {
            g_scores[(size_t)t * NEXP + tx * 8 + j] = 1.f / (1.f + expf(-acc[i][j]));
        }
    }
}

// ---------------- grouped top-k routing (exact) ------------------------------
__global__ void topk_kernel(const float* __restrict__ bias) {
    int t = blockIdx.x * blockDim.x + threadIdx.x;
    if (t >= TOKENS) return;

    float sraw[NEXP], sb[NEXP];
    const float* sc = g_scores + (size_t)t * NEXP;
#pragma unroll
    for (int e = 0; e < NEXP; e++) { sraw[e] = sc[e]; sb[e] = sraw[e] + bias[e]; }

    float gs[NGRP];
#pragma unroll
    for (int g = 0; g < NGRP; g++) {
        float m1 = -1e30f, m2 = -1e30f;
#pragma unroll
        for (int j = 0; j < NEXP / NGRP; j++) {
            float v = sb[g * (NEXP / NGRP) + j];
            if (v > m1) { m2 = m1; m1 = v; } else if (v > m2) { m2 = v; }
        }
        gs[g] = m1 + m2;
    }

    unsigned gsel = 0;
    for (int it = 0; it < TOPKG; it++) {
        int best = -1; float bv = -1e30f;
#pragma unroll
        for (int g = 0; g < NGRP; g++)
            if (!((gsel >> g) & 1u) && gs[g] > bv) { bv = gs[g]; best = g; }
        gsel |= 1u << best;
    }

    unsigned long long esel = 0ull;
    int   ids[TOPK];
    float w[TOPK];
    float wsum = 0.f;
    for (int it = 0; it < TOPK; it++) {
        int best = -1; float bv = -1e30f;
#pragma unroll
        for (int e = 0; e < NEXP; e++) {
            if (((gsel >> (e >> 3)) & 1u) && !((esel >> e) & 1ull)) {
                float v = sb[e];
                if (v > bv) { bv = v; best = e; }
            }
        }
        esel |= 1ull << best;
        ids[it] = best;
        w[it]   = sraw[best];
        wsum   += sraw[best];
    }
    float inv = 1.f / wsum;

    for (int it = 0; it < TOPK; it++) {
        int e   = ids[it];
        int pos = atomicAdd(&g_cnt[e], 1);
        g_tok[e * TOKENS + pos] = t;
        g_wt[e * TOKENS + pos]  = w[it] * inv;
    }
}

// ---------------- expert GEMM1 (fp16, BK=64, 3-stage): h = swiglu ------------
// block 128 tokens x (64 gate + 64 up), 256 thr, 8 warps 64x32
__global__ __launch_bounds__(256, 2) void w13_k() {
    extern __shared__ char smem[];
    int* stok = (int*)smem;

    const int e   = blockIdx.z;
    const int cnt = g_cnt[e];
    const int m0  = blockIdx.y * 128;
    if (m0 >= cnt) return;
    const int n0  = blockIdx.x * 64;

    const int tid = threadIdx.x, lane = tid & 31, wid = tid >> 5;
    const int wm = wid & 1, wn = wid >> 1, t4 = lane & 3, g8 = lane >> 2;

    if (tid < 128) stok[tid] = (m0 + tid < cnt) ? g_tok[e * TOKENS + m0 + tid] : -1;
    __syncthreads();

    const uint32_t sbase = smem_u32(smem);

    // loader: 4 A chunks + 4 B chunks of 16B per thread per stage (BK=64)
    const __half* asrc[4]; uint32_t asz[4], aoff[4];
    const __half* bsrc[4];
    const __half* w13e = g_w13h + (size_t)e * (2 * INTER) * HID;
#pragma unroll
    for (int p = 0; p < 4; p++) {
        int q   = tid + p * 256;
        int row = q >> 3, c = q & 7;
        int tk  = stok[row];
        asrc[p] = g_xh + (size_t)(tk >= 0 ? tk : 0) * HID + c * 8;
        asz[p]  = (tk >= 0) ? 16u : 0u;
        aoff[p] = row * ROWB + c * 16;
        int bw  = (row < 64) ? (n0 + row) : (INTER + n0 + (row - 64));
        bsrc[p] = w13e + (size_t)bw * HID + c * 8;
    }
    auto load_stage = [&](int s, int k0) {
#pragma unroll
        for (int p = 0; p < 4; p++) {
            cpa16(sbase + SA_OFF + s * STG + aoff[p], asrc[p] + k0, asz[p]);
            cpa16(sbase + SB_OFF + s * STG + aoff[p], bsrc[p] + k0, 16u);
        }
    };

    const int lr  = ((lane >> 3) & 1) * 8 + (lane & 7);
    const int lkb = (lane >> 4) * 16;
    const uint32_t aAddr = sbase + SA_OFF + (wm * 64 + lr) * ROWB + lkb;
    const uint32_t bAddr = sbase + SB_OFF + (wn * 16 + lr) * ROWB + lkb;

    float acc[4][4][4];
#pragma unroll
    for (int i = 0; i < 4; i++)
#pragma unroll
        for (int j = 0; j < 4; j++)
#pragma unroll
            for (int c = 0; c < 4; c++) acc[i][j][c] = 0.f;

    // prologue: stages 0,1
    load_stage(0, 0);  CP_COMMIT();
    load_stage(1, 64); CP_COMMIT();

    const int NIT = HID / 64;   // 16
    int s = 0, sl = 2;
    for (int it = 0; it < NIT; it++) {
        CP_WAIT1();
        __syncthreads();
        if (it + 2 < NIT) load_stage(sl, (it + 2) * 64);
        CP_COMMIT();

        const uint32_t sOff = s * STG;
#pragma unroll
        for (int ks = 0; ks < 4; ks++) {
            uint32_t a[4][4], bg[4], bu[4];
#pragma unroll
            for (int mf = 0; mf < 4; mf++)
                ldsm_x4(a[mf], aAddr + sOff + mf * 16 * ROWB + ks * 32);
            ldsm_x4(bg, bAddr + sOff + ks * 32);              // gate cols
            ldsm_x4(bu, bAddr + sOff + 64 * ROWB + ks * 32);  // up cols
#pragma unroll
            for (int mf = 0; mf < 4; mf++) {
                mma_f16(acc[mf][0], a[mf], bg[0], bg[2]);
                mma_f16(acc[mf][1], a[mf], bg[1], bg[3]);
                mma_f16(acc[mf][2], a[mf], bu[0], bu[2]);
                mma_f16(acc[mf][3], a[mf], bu[1], bu[3]);
            }
        }
        if (++s == NSTAGE) s = 0;
        if (++sl == NSTAGE) sl = 0;
    }

    // epilogue: SwiGLU fuse gate (nf 0,1) with up (nf 2,3) -> fp16 g_h
#pragma unroll
    for (int mf = 0; mf < 4; mf++) {
        int r0 = wm * 64 + mf * 16 + g8;
        int r1 = r0 + 8;
#pragma unroll
        for (int nf = 0; nf < 2; nf++) {
            int c = n0 + wn * 16 + nf * 8 + t4 * 2;
            if (m0 + r0 < cnt) {
                uint32_t o = packh2(silu(acc[mf][nf][0]) * acc[mf][nf + 2][0],
                                    silu(acc[mf][nf][1]) * acc[mf][nf + 2][1]);
                *(uint32_t*)&g_h[((size_t)e * TOKENS + m0 + r0) * INTER + c] = o;
            }
            if (m0 + r1 < cnt) {
                uint32_t o = packh2(silu(acc[mf][nf][2]) * acc[mf][nf + 2][2],
                                    silu(acc[mf][nf][3]) * acc[mf][nf + 2][3]);
                *(uint32_t*)&g_h[((size_t)e * TOKENS + m0 + r1) * INTER + c] = o;
            }
        }
    }
}

// ---------------- expert GEMM2 (fp16, BK=64, 3-stage): y += wt*(h@W2^T) ------
// block 128 slots x 128 hid cols, K=512
__global__ __launch_bounds__(256, 2) void w2_k(float* __restrict__ y) {
    extern __shared__ char smem[];
    int*   stok = (int*)smem;
    float* swt  = (float*)(smem + 512);

    const int e   = blockIdx.z;
    const int cnt = g_cnt[e];
    const int m0  = blockIdx.y * 128;
    if (m0 >= cnt) return;
    const int n0  = blockIdx.x * 128;

    const int tid = threadIdx.x, lane = tid & 31, wid = tid >> 5;
    const int wm = wid & 1, wn = wid >> 1, t4 = lane & 3, g8 = lane >> 2;

    if (tid < 128) {
        bool v = m0 + tid < cnt;
        stok[tid] = v ? g_tok[e * TOKENS + m0 + tid] : 0;
        swt[tid]  = v ? g_wt[e * TOKENS + m0 + tid] : 0.f;
    }
    __syncthreads();

    const uint32_t sbase = smem_u32(smem);

    const __half* asrc[4]; uint32_t asz[4], aoff[4];
    const __half* bsrc[4];
    const __half* w2e = g_w2h + (size_t)e * HID * INTER;
#pragma unroll
    for (int p = 0; p < 4; p++) {
        int q   = tid + p * 256;
        int row = q >> 3, c = q & 7;
        bool v  = (m0 + row) < cnt;
        asrc[p] = g_h + ((size_t)e * TOKENS + m0 + row) * INTER + c * 8;
        asz[p]  = v ? 16u : 0u;
        aoff[p] = row * ROWB + c * 16;
        bsrc[p] = w2e + (size_t)(n0 + row) * INTER + c * 8;
    }
    auto load_stage = [&](int s, int k0) {
#pragma unroll
        for (int p = 0; p < 4; p++) {
            cpa16(sbase + SA_OFF + s * STG + aoff[p], asrc[p] + k0, asz[p]);
            cpa16(sbase + SB_OFF + s * STG + aoff[p], bsrc[p] + k0, 16u);
        }
    };

    const int lr  = ((lane >> 3) & 1) * 8 + (lane & 7);
    const int lkb = (lane >> 4) * 16;
    const uint32_t aAddr = sbase + SA_OFF + (wm * 64 + lr) * ROWB + lkb;
    const uint32_t bAddr = sbase + SB_OFF + (wn * 32 + lr) * ROWB + lkb;

    float acc[4][4][4];
#pragma unroll
    for (int i = 0; i < 4; i++)
#pragma unroll
        for (int j = 0; j < 4; j++)
#pragma unroll
            for (int c = 0; c < 4; c++) acc[i][j][c] = 0.f;

    load_stage(0, 0);  CP_COMMIT();
    load_stage(1, 64); CP_COMMIT();

    const int NIT = INTER / 64;   // 8
    int s = 0, sl = 2;
    for (int it = 0; it < NIT; it++) {
        CP_WAIT1();
        __syncthreads();
        if (it + 2 < NIT) load_stage(sl, (it + 2) * 64);
        CP_COMMIT();

        const uint32_t sOff = s * STG;
#pragma unroll
        for (int ks = 0; ks < 4; ks++) {
            uint32_t a[4][4], b0[4], b1[4];
#pragma unroll
            for (int mf = 0; mf < 4; mf++)
                ldsm_x4(a[mf], aAddr + sOff + mf * 16 * ROWB + ks * 32);
            ldsm_x4(b0, bAddr + sOff + ks * 32);              // cols 0-15
            ldsm_x4(b1, bAddr + sOff + 16 * ROWB + ks * 32);  // cols 16-31
#pragma unroll
            for (int mf = 0; mf < 4; mf++) {
                mma_f16(acc[mf][0], a[mf], b0[0], b0[2]);
                mma_f16(acc[mf][1], a[mf], b0[1], b0[3]);
                mma_f16(acc[mf][2], a[mf], b1[0], b1[2]);
                mma_f16(acc[mf][3], a[mf], b1[1], b1[3]);
            }
        }
        if (++s == NSTAGE) s = 0;
        if (++sl == NSTAGE) sl = 0;
    }

    // epilogue: scaled reductions into y
#pragma unroll
    for (int mf = 0; mf < 4; mf++) {
        int r0 = wm * 64 + mf * 16 + g8;
        int r1 = r0 + 8;
        bool v0 = (m0 + r0) < cnt;
        bool v1 = (m0 + r1) < cnt;
        int   tok0 = stok[r0], tok1 = stok[r1];
        float wt0 = swt[r0],  wt1 = swt[r1];
#pragma unroll
        for (int nf = 0; nf < 4; nf++) {
            int c = n0 + wn * 32 + nf * 8 + t4 * 2;
            if (v0) red_add_v2(&y[(size_t)tok0 * HID + c],
                               wt0 * acc[mf][nf][0], wt0 * acc[mf][nf][1]);
            if (v1) red_add_v2(&y[(size_t)tok1 * HID + c],
                               wt1 * acc[mf][nf][2], wt1 * acc[mf][nf][3]);
        }
    }
}

// ---------------- launch ------------------------------------------------------
extern "C" void kernel_launch(void* const* d_in, const int* in_sizes, int n_in,
                              void* d_out, int out_size) {
    const float* x    = (const float*)d_in[0];   // [2048,1024]
    const float* gw   = (const float*)d_in[1];   // [64,1024]
    const float* bias = (const float*)d_in[2];   // [64]
    const float* w13  = (const float*)d_in[3];   // [64,1024,1024]
    const float* w2   = (const float*)d_in[4];   // [64,1024,512]
    float* y = (float*)d_out;                    // [2048,1024]

    cudaFuncSetAttribute(w13_k, cudaFuncAttributeMaxDynamicSharedMemorySize, SM_TOT);
    cudaFuncSetAttribute(w2_k,  cudaFuncAttributeMaxDynamicSharedMemorySize, SM_TOT);

    __half *d_w13h, *d_w2h, *d_xh;
    cudaGetSymbolAddress((void**)&d_w13h, g_w13h);
    cudaGetSymbolAddress((void**)&d_w2h,  g_w2h);
    cudaGetSymbolAddress((void**)&d_xh,   g_xh);

    cudaMemsetAsync(y, 0, (size_t)TOKENS * HID * sizeof(float), 0);
    zero_cnt_kernel<<<1, 64>>>();
    {
        int n4 = NEXP * 2 * INTER * HID / 8;
        conv_kernel<<<n4 / 256 / 2, 256>>>((const float4*)w13, (uint4*)d_w13h, n4);
        n4 = NEXP * HID * INTER / 8;
        conv_kernel<<<n4 / 256 / 2, 256>>>((const float4*)w2, (uint4*)d_w2h, n4);
        n4 = TOKENS * HID / 8;
        conv_kernel<<<n4 / 256, 256>>>((const float4*)x, (uint4*)d_xh, n4);
    }
    router_kernel<<<TOKENS / 128, 128>>>(x, gw);
    topk_kernel<<<TOKENS / 256, 256>>>(bias);
    w13_k<<<dim3(INTER / 64, TOKENS / 128, NEXP), 256, SM_TOT>>>();
    w2_k<<<dim3(HID / 128, TOKENS / 128, NEXP), 256, SM_TOT>>>(y);
}